// round 1
// baseline (speedup 1.0000x reference)
#include <cuda_runtime.h>
#include <cuda_bf16.h>
#include <mma.h>
#include <math.h>

using namespace nvcuda;

// Problem constants
#define T_TOK 8192
#define HID   2048
#define NEXP  64
#define IDIM  768
#define TOPK  8
#define TK    (T_TOK*TOPK)          // 65536 token-expert pairs
#define TILE_M 128
#define MAX_TILES ((TK/TILE_M) + NEXP)   // 512 + 64 = 576
#define MAXPAD (MAX_TILES*TILE_M)        // 73728 padded pair slots

// ---------------- scratch (device globals; allocation-free) ----------------
__device__ int   g_topk_e[TK];
__device__ float g_topk_w[TK];
__device__ int   g_counts[NEXP];
__device__ int   g_cursor[NEXP];
__device__ int   g_tile_expert[MAX_TILES];
__device__ int   g_token_list[MAXPAD];
__device__ int   g_pair_slot[TK];
__device__ float g_act[(size_t)MAXPAD * IDIM];      // gate then act=silu(g)*u
__device__ float g_pairout[(size_t)MAXPAD * HID];   // per-pair down output

// ---------------- reset ----------------
__global__ void k_reset() {
    int idx = blockIdx.x * blockDim.x + threadIdx.x;
    if (idx < MAXPAD)    g_token_list[idx] = -1;
    if (idx < MAX_TILES) g_tile_expert[idx] = -1;
    if (idx < NEXP)      g_counts[idx] = 0;
}

// ---------------- router: fp32 logits, softmax, top-8, renorm ----------------
// 16 tokens per block, 256 threads.
__global__ __launch_bounds__(256) void k_router(
    const float* __restrict__ x, const float* __restrict__ gw,
    float* __restrict__ out_logits, int write_logits)
{
    __shared__ float xs[16 * 64];       // [tok][k] chunk
    __shared__ float ws[64 * 65];       // [expert][k] chunk, pad 65 (conflict-free)
    __shared__ float lg[16 * 65];       // [tok][expert] logits/probs

    int tid = threadIdx.x;
    int tok0 = blockIdx.x * 16;

    int e  = tid & 63;
    int tr = tid >> 6;                  // 0..3, handles tokens tr*4 .. tr*4+3
    float acc0 = 0.f, acc1 = 0.f, acc2 = 0.f, acc3 = 0.f;

    for (int kc = 0; kc < HID; kc += 64) {
        // load x chunk: 16 tokens x 64 floats (float4)
        {
            int r  = tid >> 4;          // 0..15
            int c4 = tid & 15;          // 0..15 float4 cols
            float4 v = *(const float4*)(x + (size_t)(tok0 + r) * HID + kc + c4 * 4);
            *(float4*)&xs[r * 64 + c4 * 4] = v;
        }
        // load gate_weight chunk: 64 experts x 64 floats (scalar, padded smem)
        #pragma unroll
        for (int p = 0; p < 16; p++) {
            int lin = p * 256 + tid;
            int r = lin >> 6, c = lin & 63;
            ws[r * 65 + c] = gw[(size_t)r * HID + kc + c];
        }
        __syncthreads();
        #pragma unroll 8
        for (int kk = 0; kk < 64; kk++) {
            float wv = ws[e * 65 + kk];
            acc0 += xs[(tr * 4 + 0) * 64 + kk] * wv;
            acc1 += xs[(tr * 4 + 1) * 64 + kk] * wv;
            acc2 += xs[(tr * 4 + 2) * 64 + kk] * wv;
            acc3 += xs[(tr * 4 + 3) * 64 + kk] * wv;
        }
        __syncthreads();
    }
    lg[(tr * 4 + 0) * 65 + e] = acc0;
    lg[(tr * 4 + 1) * 65 + e] = acc1;
    lg[(tr * 4 + 2) * 65 + e] = acc2;
    lg[(tr * 4 + 3) * 65 + e] = acc3;
    __syncthreads();

    // write raw logits output
    if (write_logits) {
        #pragma unroll
        for (int p = 0; p < 4; p++) {
            int lin = p * 256 + tid;
            int t = lin >> 6, ee = lin & 63;
            out_logits[(size_t)(tok0 + t) * NEXP + ee] = lg[t * 65 + ee];
        }
    }

    // per-token softmax + top-8 + renorm (serial per token; 16 tokens parallel)
    if (tid < 16) {
        int t = tid;
        float* l = &lg[t * 65];
        float m = -1e30f;
        for (int i = 0; i < NEXP; i++) m = fmaxf(m, l[i]);
        for (int i = 0; i < NEXP; i++) l[i] = expf(l[i] - m);   // unnormalized probs (norm cancels)
        int   sel[TOPK];
        float sp[TOPK];
        float wsum = 0.f;
        #pragma unroll
        for (int k = 0; k < TOPK; k++) {
            float bp = -1.f; int be = -1;
            for (int i = 0; i < NEXP; i++) {
                if (l[i] > bp) { bp = l[i]; be = i; }   // strict > : lowest index on ties
            }
            sel[k] = be; sp[k] = bp; wsum += bp;
            l[be] = -1.f;
        }
        float inv = 1.f / wsum;
        #pragma unroll
        for (int k = 0; k < TOPK; k++) {
            int idx = (tok0 + t) * TOPK + k;
            g_topk_e[idx] = sel[k];
            g_topk_w[idx] = sp[k] * inv;
            atomicAdd(&g_counts[sel[k]], 1);
        }
    }
}

// ---------------- scan: build tile schedule (segments 128-aligned) ----------------
__global__ void k_scan() {
    if (threadIdx.x == 0 && blockIdx.x == 0) {
        int tile = 0;
        for (int e = 0; e < NEXP; e++) {
            int n = g_counts[e];
            g_cursor[e] = tile * TILE_M;
            int nt = (n + TILE_M - 1) / TILE_M;
            for (int i = 0; i < nt; i++) g_tile_expert[tile + i] = e;
            tile += nt;
        }
    }
}

// ---------------- fill gathered token lists ----------------
__global__ void k_fill() {
    int idx = blockIdx.x * blockDim.x + threadIdx.x;
    if (idx < TK) {
        int e = g_topk_e[idx];
        int p = atomicAdd(&g_cursor[e], 1);
        g_token_list[p] = idx >> 3;     // token id
        g_pair_slot[idx] = p;
    }
}

// ---------------- grouped GEMM (tf32 wmma), 128x64 block tile, BK=32 ----------------
// MODE 0: C(g_act)    = gather(X) @ gate_proj[e]^T              (KD=HID, ND=IDIM)
// MODE 1: C(g_act)    = silu(g_act) * (gather(X) @ up_proj[e]^T)
// MODE 2: C(g_pairout)= g_act @ down_proj[e]^T                  (KD=IDIM, ND=HID)
template<int KD, int ND, int MODE>
__global__ __launch_bounds__(256) void k_gemm(
    const float* __restrict__ Aglob, const float* __restrict__ Bglob)
{
    int tileM = blockIdx.x;
    int eid = g_tile_expert[tileM];
    if (eid < 0) return;
    int slot0 = tileM * TILE_M;
    int n0 = blockIdx.y * 64;

    const float* Bexp = Bglob + (size_t)eid * ND * KD;   // [ND][KD] row-major

    __shared__ float sm[8704];          // As(128x36) + Bs(64x36) | Cs(128x68)
    float* As = sm;
    float* Bs = sm + 128 * 36;
    __shared__ int toks[TILE_M];

    int tid = threadIdx.x;
    if (MODE < 2) {
        if (tid < TILE_M) toks[tid] = g_token_list[slot0 + tid];
    }
    __syncthreads();

    typedef wmma::fragment<wmma::matrix_a, 16, 16, 8, wmma::precision::tf32, wmma::row_major> FragA;
    typedef wmma::fragment<wmma::matrix_b, 16, 16, 8, wmma::precision::tf32, wmma::col_major> FragB;
    typedef wmma::fragment<wmma::accumulator, 16, 16, 8, float> FragC;

    FragC c[2][2];
    #pragma unroll
    for (int i = 0; i < 2; i++)
        #pragma unroll
        for (int j = 0; j < 2; j++)
            wmma::fill_fragment(c[i][j], 0.f);

    int wid = tid >> 5;
    int wm = wid & 3;       // 0..3 (m)
    int wn = wid >> 2;      // 0..1 (n)

    for (int k0 = 0; k0 < KD; k0 += 32) {
        // load A tile 128x32
        #pragma unroll
        for (int p = 0; p < 4; p++) {
            int lin = p * 256 + tid;
            int r = lin >> 3, c4 = lin & 7;
            float4 v;
            if (MODE < 2) {
                int tok = toks[r];
                if (tok >= 0)
                    v = *(const float4*)(Aglob + (size_t)tok * KD + k0 + c4 * 4);
                else
                    v = make_float4(0.f, 0.f, 0.f, 0.f);
            } else {
                v = *(const float4*)(g_act + (size_t)(slot0 + r) * KD + k0 + c4 * 4);
            }
            *(float4*)&As[r * 36 + c4 * 4] = v;
        }
        // load B tile 64x32
        #pragma unroll
        for (int p = 0; p < 2; p++) {
            int lin = p * 256 + tid;
            int r = lin >> 3, c4 = lin & 7;
            *(float4*)&Bs[r * 36 + c4 * 4] =
                *(const float4*)(Bexp + (size_t)(n0 + r) * KD + k0 + c4 * 4);
        }
        __syncthreads();

        #pragma unroll
        for (int kk = 0; kk < 32; kk += 8) {
            FragA a[2]; FragB b[2];
            wmma::load_matrix_sync(a[0], As + (wm * 32) * 36 + kk, 36);
            wmma::load_matrix_sync(a[1], As + (wm * 32 + 16) * 36 + kk, 36);
            wmma::load_matrix_sync(b[0], Bs + (wn * 32) * 36 + kk, 36);
            wmma::load_matrix_sync(b[1], Bs + (wn * 32 + 16) * 36 + kk, 36);
            #pragma unroll
            for (int i = 0; i < a[0].num_elements; i++) {
                a[0].x[i] = wmma::__float_to_tf32(a[0].x[i]);
                a[1].x[i] = wmma::__float_to_tf32(a[1].x[i]);
            }
            #pragma unroll
            for (int i = 0; i < b[0].num_elements; i++) {
                b[0].x[i] = wmma::__float_to_tf32(b[0].x[i]);
                b[1].x[i] = wmma::__float_to_tf32(b[1].x[i]);
            }
            wmma::mma_sync(c[0][0], a[0], b[0], c[0][0]);
            wmma::mma_sync(c[0][1], a[0], b[1], c[0][1]);
            wmma::mma_sync(c[1][0], a[1], b[0], c[1][0]);
            wmma::mma_sync(c[1][1], a[1], b[1], c[1][1]);
        }
        __syncthreads();
    }

    if (MODE == 0) {
        #pragma unroll
        for (int mi = 0; mi < 2; mi++)
            #pragma unroll
            for (int ni = 0; ni < 2; ni++)
                wmma::store_matrix_sync(
                    g_act + (size_t)(slot0 + wm * 32 + mi * 16) * ND + n0 + wn * 32 + ni * 16,
                    c[mi][ni], ND, wmma::mem_row_major);
    } else if (MODE == 2) {
        #pragma unroll
        for (int mi = 0; mi < 2; mi++)
            #pragma unroll
            for (int ni = 0; ni < 2; ni++)
                wmma::store_matrix_sync(
                    g_pairout + (size_t)(slot0 + wm * 32 + mi * 16) * ND + n0 + wn * 32 + ni * 16,
                    c[mi][ni], ND, wmma::mem_row_major);
    } else {
        // MODE 1: stage u tile in smem, fuse act = silu(g)*u, overwrite g_act
        float* Cs = sm;                 // 128 x 68
        #pragma unroll
        for (int mi = 0; mi < 2; mi++)
            #pragma unroll
            for (int ni = 0; ni < 2; ni++)
                wmma::store_matrix_sync(
                    Cs + (wm * 32 + mi * 16) * 68 + wn * 32 + ni * 16,
                    c[mi][ni], 68, wmma::mem_row_major);
        __syncthreads();
        #pragma unroll
        for (int p = 0; p < 32; p++) {
            int lin = p * 256 + tid;
            int m = lin >> 6, n = lin & 63;
            size_t gi = (size_t)(slot0 + m) * ND + n0 + n;
            float g = g_act[gi];
            float u = Cs[m * 68 + n];
            g_act[gi] = (g / (1.f + expf(-g))) * u;
        }
    }
}

// ---------------- deterministic combine: out[t] = sum_k w[t,k] * pairout[slot(t,k)] ----
__global__ __launch_bounds__(256) void k_combine(float* __restrict__ out) {
    size_t idx = (size_t)blockIdx.x * 256 + threadIdx.x;   // over T*H
    int t = (int)(idx >> 11);       // /HID
    int h = (int)(idx & 2047);
    float s = 0.f;
    #pragma unroll
    for (int k = 0; k < TOPK; k++) {
        int pi = t * TOPK + k;
        int p = g_pair_slot[pi];
        s += g_topk_w[pi] * g_pairout[(size_t)p * HID + h];
    }
    out[idx] = s;
}

// ---------------- launch ----------------
extern "C" void kernel_launch(void* const* d_in, const int* in_sizes, int n_in,
                              void* d_out, int out_size) {
    const float* x  = (const float*)d_in[0];   // [T, H]
    const float* gw = (const float*)d_in[1];   // [E, H]
    const float* gp = (const float*)d_in[2];   // [E, I, H]
    const float* up = (const float*)d_in[3];   // [E, I, H]
    const float* dp = (const float*)d_in[4];   // [E, H, I]
    float* out = (float*)d_out;
    float* out_logits = out + (size_t)T_TOK * HID;
    int write_logits = (out_size >= T_TOK * HID + T_TOK * NEXP) ? 1 : 0;

    k_reset<<<(MAXPAD + 255) / 256, 256>>>();
    k_router<<<T_TOK / 16, 256>>>(x, gw, out_logits, write_logits);
    k_scan<<<1, 32>>>();
    k_fill<<<(TK + 255) / 256, 256>>>();

    // gate: g_act = gather(X) @ gp[e]^T
    k_gemm<HID, IDIM, 0><<<dim3(MAX_TILES, IDIM / 64), 256>>>(x, gp);
    // up + fused SwiGLU: g_act = silu(g_act) * (gather(X) @ up[e]^T)
    k_gemm<HID, IDIM, 1><<<dim3(MAX_TILES, IDIM / 64), 256>>>(x, up);
    // down: g_pairout = g_act @ dp[e]^T
    k_gemm<IDIM, HID, 2><<<dim3(MAX_TILES, HID / 64), 256>>>(x, dp);

    k_combine<<<(T_TOK * (HID / 256)), 256>>>(out);
}

// round 2
// speedup vs baseline: 1.0494x; 1.0494x over previous
#include <cuda_runtime.h>
#include <cuda_bf16.h>
#include <mma.h>
#include <math.h>
#include <stdint.h>

using namespace nvcuda;

// Problem constants
#define T_TOK 8192
#define HID   2048
#define NEXP  64
#define IDIM  768
#define TOPK  8
#define TK    (T_TOK*TOPK)               // 65536 token-expert pairs
#define TILE_M 128
#define MAX_TILES ((TK/TILE_M) + NEXP)   // 512 + 64 = 576
#define MAXPAD (MAX_TILES*TILE_M)        // 73728 padded pair slots

// smem geometry for GEMM (floats)
#define BK 32
#define AS_STRIDE 36                     // 32 + 4 pad, keeps 16B alignment
#define STAGE_FL (128*AS_STRIDE)         // floats per (A or B) stage
#define GEMM_SMEM_BYTES (4*STAGE_FL*4)   // 2 stages A + 2 stages B = 73728 B
#define CS_STRIDE 136                    // epilogue staging stride (<= smem)

// ---------------- scratch (device globals; allocation-free) ----------------
__device__ int   g_topk_e[TK];
__device__ float g_topk_w[TK];
__device__ int   g_counts[NEXP];
__device__ int   g_cursor[NEXP];
__device__ int   g_tile_expert[MAX_TILES];
__device__ int   g_token_list[MAXPAD];
__device__ int   g_pair_slot[TK];
__device__ float g_act[(size_t)MAXPAD * IDIM];      // gate, then act=silu(g)*u
__device__ float g_pairout[(size_t)MAXPAD * HID];   // per-pair down output

// ---------------- cp.async helpers ----------------
__device__ __forceinline__ void cp_async16(uint32_t dst, const void* src, int src_bytes) {
    asm volatile("cp.async.cg.shared.global [%0], [%1], 16, %2;\n"
                 :: "r"(dst), "l"(src), "r"(src_bytes));
}
__device__ __forceinline__ void cp_commit() { asm volatile("cp.async.commit_group;\n"); }
__device__ __forceinline__ void cp_wait0()  { asm volatile("cp.async.wait_group 0;\n"); }

// ---------------- reset ----------------
__global__ void k_reset() {
    int idx = blockIdx.x * blockDim.x + threadIdx.x;
    if (idx < MAXPAD)    g_token_list[idx] = -1;
    if (idx < MAX_TILES) g_tile_expert[idx] = -1;
    if (idx < NEXP)      g_counts[idx] = 0;
}

// ---------------- router: fp32 logits, softmax, top-8, renorm ----------------
__global__ __launch_bounds__(256) void k_router(
    const float* __restrict__ x, const float* __restrict__ gw,
    float* __restrict__ out_logits, int write_logits)
{
    __shared__ float xs[16 * 64];
    __shared__ float ws[64 * 65];
    __shared__ float lg[16 * 65];

    int tid = threadIdx.x;
    int tok0 = blockIdx.x * 16;

    int e  = tid & 63;
    int tr = tid >> 6;
    float acc0 = 0.f, acc1 = 0.f, acc2 = 0.f, acc3 = 0.f;

    for (int kc = 0; kc < HID; kc += 64) {
        {
            int r  = tid >> 4;
            int c4 = tid & 15;
            float4 v = *(const float4*)(x + (size_t)(tok0 + r) * HID + kc + c4 * 4);
            *(float4*)&xs[r * 64 + c4 * 4] = v;
        }
        #pragma unroll
        for (int p = 0; p < 16; p++) {
            int lin = p * 256 + tid;
            int r = lin >> 6, c = lin & 63;
            ws[r * 65 + c] = gw[(size_t)r * HID + kc + c];
        }
        __syncthreads();
        #pragma unroll 8
        for (int kk = 0; kk < 64; kk++) {
            float wv = ws[e * 65 + kk];
            acc0 += xs[(tr * 4 + 0) * 64 + kk] * wv;
            acc1 += xs[(tr * 4 + 1) * 64 + kk] * wv;
            acc2 += xs[(tr * 4 + 2) * 64 + kk] * wv;
            acc3 += xs[(tr * 4 + 3) * 64 + kk] * wv;
        }
        __syncthreads();
    }
    lg[(tr * 4 + 0) * 65 + e] = acc0;
    lg[(tr * 4 + 1) * 65 + e] = acc1;
    lg[(tr * 4 + 2) * 65 + e] = acc2;
    lg[(tr * 4 + 3) * 65 + e] = acc3;
    __syncthreads();

    if (write_logits) {
        #pragma unroll
        for (int p = 0; p < 4; p++) {
            int lin = p * 256 + tid;
            int t = lin >> 6, ee = lin & 63;
            out_logits[(size_t)(tok0 + t) * NEXP + ee] = lg[t * 65 + ee];
        }
    }

    if (tid < 16) {
        int t = tid;
        float* l = &lg[t * 65];
        float m = -1e30f;
        for (int i = 0; i < NEXP; i++) m = fmaxf(m, l[i]);
        for (int i = 0; i < NEXP; i++) l[i] = expf(l[i] - m);
        int   sel[TOPK];
        float sp[TOPK];
        float wsum = 0.f;
        #pragma unroll
        for (int k = 0; k < TOPK; k++) {
            float bp = -1.f; int be = -1;
            for (int i = 0; i < NEXP; i++)
                if (l[i] > bp) { bp = l[i]; be = i; }
            sel[k] = be; sp[k] = bp; wsum += bp;
            l[be] = -1.f;
        }
        float inv = 1.f / wsum;
        #pragma unroll
        for (int k = 0; k < TOPK; k++) {
            int idx = (tok0 + t) * TOPK + k;
            g_topk_e[idx] = sel[k];
            g_topk_w[idx] = sp[k] * inv;
            atomicAdd(&g_counts[sel[k]], 1);
        }
    }
}

// ---------------- scan: build tile schedule ----------------
__global__ void k_scan() {
    if (threadIdx.x == 0 && blockIdx.x == 0) {
        int tile = 0;
        for (int e = 0; e < NEXP; e++) {
            int n = g_counts[e];
            g_cursor[e] = tile * TILE_M;
            int nt = (n + TILE_M - 1) / TILE_M;
            for (int i = 0; i < nt; i++) g_tile_expert[tile + i] = e;
            tile += nt;
        }
    }
}

// ---------------- fill gathered token lists ----------------
__global__ void k_fill() {
    int idx = blockIdx.x * blockDim.x + threadIdx.x;
    if (idx < TK) {
        int e = g_topk_e[idx];
        int p = atomicAdd(&g_cursor[e], 1);
        g_token_list[p] = idx >> 3;
        g_pair_slot[idx] = p;
    }
}

// ---------------- grouped GEMM (tf32 wmma), 128x128 tile, BK=32, 2-stage cp.async ----
// MODE 0: g_act     = gather(X) @ gate_proj[e]^T   (KD=HID, ND=IDIM)
// MODE 1: g_act     = silu(g_act) * (gather(X) @ up_proj[e]^T)
// MODE 2: g_pairout = g_act @ down_proj[e]^T       (KD=IDIM, ND=HID)
template<int KD, int ND, int MODE>
__global__ __launch_bounds__(256, 1) void k_gemm(
    const float* __restrict__ Aglob, const float* __restrict__ Bglob)
{
    extern __shared__ float sm[];
    float* Asm = sm;                      // 2 stages, each 128 x AS_STRIDE
    float* Bsm = sm + 2 * STAGE_FL;       // 2 stages

    int tileM = blockIdx.x;
    int eid = g_tile_expert[tileM];
    if (eid < 0) return;
    int slot0 = tileM * TILE_M;
    int n0 = blockIdx.y * 128;

    const float* Bexp = Bglob + (size_t)eid * ND * KD;

    __shared__ int toks[TILE_M];
    int tid = threadIdx.x;
    if (MODE < 2) {
        if (tid < TILE_M) toks[tid] = g_token_list[slot0 + tid];
    }
    __syncthreads();

    // per-thread load coordinates (4 float4's for A, 4 for B per stage)
    int lr = tid >> 3;        // base row 0..31 (advances by 32 per p)
    int lc4 = tid & 7;        // float4 column 0..7

    uint32_t s_base = (uint32_t)__cvta_generic_to_shared(sm);

    // issue loads for stage s at k-offset k0
    auto issue = [&](int s, int k0) {
        uint32_t a_dst = s_base + (uint32_t)(s * STAGE_FL) * 4;
        uint32_t b_dst = s_base + (uint32_t)((2 + s) * STAGE_FL) * 4;
        #pragma unroll
        for (int p = 0; p < 4; p++) {
            int r = lr + p * 32;
            uint32_t doff = (uint32_t)(r * AS_STRIDE + lc4 * 4) * 4;
            // A row
            const float* asrc;
            int asz = 16;
            if (MODE < 2) {
                int tok = toks[r];
                asrc = Aglob + (size_t)(tok < 0 ? 0 : tok) * KD + k0 + lc4 * 4;
                asz = (tok < 0) ? 0 : 16;
            } else {
                asrc = g_act + (size_t)(slot0 + r) * KD + k0 + lc4 * 4;
            }
            cp_async16(a_dst + doff, asrc, asz);
            // B row
            const float* bsrc = Bexp + (size_t)(n0 + r) * KD + k0 + lc4 * 4;
            cp_async16(b_dst + doff, bsrc, 16);
        }
        cp_commit();
    };

    typedef wmma::fragment<wmma::matrix_a, 16, 16, 8, wmma::precision::tf32, wmma::row_major> FragA;
    typedef wmma::fragment<wmma::matrix_b, 16, 16, 8, wmma::precision::tf32, wmma::col_major> FragB;
    typedef wmma::fragment<wmma::accumulator, 16, 16, 8, float> FragC;

    FragC c[2][4];
    #pragma unroll
    for (int i = 0; i < 2; i++)
        #pragma unroll
        for (int j = 0; j < 4; j++)
            wmma::fill_fragment(c[i][j], 0.f);

    int wid = tid >> 5;
    int wm = wid & 3;          // 0..3 -> rows wm*32
    int wn = wid >> 2;         // 0..1 -> cols wn*64

    const int KT = KD / BK;
    issue(0, 0);

    for (int kt = 0; kt < KT; kt++) {
        cp_wait0();
        __syncthreads();
        if (kt + 1 < KT) issue((kt + 1) & 1, (kt + 1) * BK);

        float* As = Asm + (kt & 1) * STAGE_FL;
        float* Bs = Bsm + (kt & 1) * STAGE_FL;

        #pragma unroll
        for (int kk = 0; kk < BK; kk += 8) {
            FragA a[2];
            FragB b[4];
            wmma::load_matrix_sync(a[0], As + (wm * 32) * AS_STRIDE + kk, AS_STRIDE);
            wmma::load_matrix_sync(a[1], As + (wm * 32 + 16) * AS_STRIDE + kk, AS_STRIDE);
            #pragma unroll
            for (int ni = 0; ni < 4; ni++)
                wmma::load_matrix_sync(b[ni], Bs + (wn * 64 + ni * 16) * AS_STRIDE + kk, AS_STRIDE);
            #pragma unroll
            for (int i = 0; i < 4; i++) {
                a[0].x[i] = wmma::__float_to_tf32(a[0].x[i]);
                a[1].x[i] = wmma::__float_to_tf32(a[1].x[i]);
                b[0].x[i] = wmma::__float_to_tf32(b[0].x[i]);
                b[1].x[i] = wmma::__float_to_tf32(b[1].x[i]);
                b[2].x[i] = wmma::__float_to_tf32(b[2].x[i]);
                b[3].x[i] = wmma::__float_to_tf32(b[3].x[i]);
            }
            #pragma unroll
            for (int mi = 0; mi < 2; mi++)
                #pragma unroll
                for (int ni = 0; ni < 4; ni++)
                    wmma::mma_sync(c[mi][ni], a[mi], b[ni], c[mi][ni]);
        }
        __syncthreads();
    }

    if (MODE == 0) {
        #pragma unroll
        for (int mi = 0; mi < 2; mi++)
            #pragma unroll
            for (int ni = 0; ni < 4; ni++)
                wmma::store_matrix_sync(
                    g_act + (size_t)(slot0 + wm * 32 + mi * 16) * ND + n0 + wn * 64 + ni * 16,
                    c[mi][ni], ND, wmma::mem_row_major);
    } else if (MODE == 2) {
        #pragma unroll
        for (int mi = 0; mi < 2; mi++)
            #pragma unroll
            for (int ni = 0; ni < 4; ni++)
                wmma::store_matrix_sync(
                    g_pairout + (size_t)(slot0 + wm * 32 + mi * 16) * ND + n0 + wn * 64 + ni * 16,
                    c[mi][ni], ND, wmma::mem_row_major);
    } else {
        // MODE 1: stage u tile in smem, fuse act = silu(g)*u
        float* Cs = sm;                   // 128 x CS_STRIDE floats (69632 B <= 73728)
        #pragma unroll
        for (int mi = 0; mi < 2; mi++)
            #pragma unroll
            for (int ni = 0; ni < 4; ni++)
                wmma::store_matrix_sync(
                    Cs + (wm * 32 + mi * 16) * CS_STRIDE + wn * 64 + ni * 16,
                    c[mi][ni], CS_STRIDE, wmma::mem_row_major);
        __syncthreads();
        #pragma unroll
        for (int p = 0; p < 16; p++) {
            int lin = p * 256 + tid;      // over 4096 float4's
            int m = lin >> 5, n4 = lin & 31;
            size_t gi = (size_t)(slot0 + m) * ND + n0 + n4 * 4;
            float4 g = *(float4*)(g_act + gi);
            float4 u = *(float4*)(Cs + m * CS_STRIDE + n4 * 4);
            float4 o;
            o.x = (g.x / (1.f + expf(-g.x))) * u.x;
            o.y = (g.y / (1.f + expf(-g.y))) * u.y;
            o.z = (g.z / (1.f + expf(-g.z))) * u.z;
            o.w = (g.w / (1.f + expf(-g.w))) * u.w;
            *(float4*)(g_act + gi) = o;
        }
    }
}

// ---------------- deterministic combine (float4) ----------------
__global__ __launch_bounds__(256) void k_combine(float* __restrict__ out) {
    size_t idx = (size_t)blockIdx.x * 256 + threadIdx.x;   // over T*H/4
    int t  = (int)(idx >> 9);           // / (HID/4)
    int h4 = (int)(idx & 511);
    float4 s = make_float4(0.f, 0.f, 0.f, 0.f);
    #pragma unroll
    for (int k = 0; k < TOPK; k++) {
        int pi = t * TOPK + k;
        int p = g_pair_slot[pi];
        float w = g_topk_w[pi];
        float4 v = *(const float4*)(g_pairout + (size_t)p * HID + h4 * 4);
        s.x += w * v.x; s.y += w * v.y; s.z += w * v.z; s.w += w * v.w;
    }
    *(float4*)(out + idx * 4) = s;
}

// ---------------- launch ----------------
extern "C" void kernel_launch(void* const* d_in, const int* in_sizes, int n_in,
                              void* d_out, int out_size) {
    const float* x  = (const float*)d_in[0];   // [T, H]
    const float* gw = (const float*)d_in[1];   // [E, H]
    const float* gp = (const float*)d_in[2];   // [E, I, H]
    const float* up = (const float*)d_in[3];   // [E, I, H]
    const float* dp = (const float*)d_in[4];   // [E, H, I]
    float* out = (float*)d_out;
    float* out_logits = out + (size_t)T_TOK * HID;
    int write_logits = (out_size >= T_TOK * HID + T_TOK * NEXP) ? 1 : 0;

    cudaFuncSetAttribute(k_gemm<HID, IDIM, 0>,
                         cudaFuncAttributeMaxDynamicSharedMemorySize, GEMM_SMEM_BYTES);
    cudaFuncSetAttribute(k_gemm<HID, IDIM, 1>,
                         cudaFuncAttributeMaxDynamicSharedMemorySize, GEMM_SMEM_BYTES);
    cudaFuncSetAttribute(k_gemm<IDIM, HID, 2>,
                         cudaFuncAttributeMaxDynamicSharedMemorySize, GEMM_SMEM_BYTES);

    k_reset<<<(MAXPAD + 255) / 256, 256>>>();
    k_router<<<T_TOK / 16, 256>>>(x, gw, out_logits, write_logits);
    k_scan<<<1, 32>>>();
    k_fill<<<(TK + 255) / 256, 256>>>();

    // gate: g_act = gather(X) @ gp[e]^T
    k_gemm<HID, IDIM, 0><<<dim3(MAX_TILES, IDIM / 128), 256, GEMM_SMEM_BYTES>>>(x, gp);
    // up + fused SwiGLU
    k_gemm<HID, IDIM, 1><<<dim3(MAX_TILES, IDIM / 128), 256, GEMM_SMEM_BYTES>>>(x, up);
    // down
    k_gemm<IDIM, HID, 2><<<dim3(MAX_TILES, HID / 128), 256, GEMM_SMEM_BYTES>>>(x, dp);

    k_combine<<<T_TOK * HID / 4 / 256, 256>>>(out);
}

// round 4
// speedup vs baseline: 1.2486x; 1.1898x over previous
#include <cuda_runtime.h>
#include <cuda_bf16.h>
#include <mma.h>
#include <math.h>
#include <stdint.h>

using namespace nvcuda;

// Problem constants
#define T_TOK 8192
#define HID   2048
#define NEXP  64
#define IDIM  768
#define TOPK  8
#define TK    (T_TOK*TOPK)               // 65536 pairs
#define TILE_M 128
#define MAX_TILES ((TK/TILE_M) + NEXP)   // 576
#define MAXPAD (MAX_TILES*TILE_M)        // 73728

// GEMM geometry: block 128x256, warp 64x64 (2x4 warps), BK=32, 3-stage cp.async
#define BK       32
#define TILE_N   256
#define AS_STRIDE 36                      // 32 + 4 pad floats (144B rows, 16B aligned)
#define A_FL     (128*AS_STRIDE)          // 4608 floats
#define B_FL     (256*AS_STRIDE)          // 9216 floats
#define ST_FL    (A_FL + B_FL)            // 13824 floats per stage
#define STAGES   3
#define GEMM_SMEM (STAGES*ST_FL*4)        // 165888 B
#define CS_STRIDE 260                     // epilogue staging stride (133120 B <= GEMM_SMEM)

// ---------------- scratch ----------------
__device__ int   g_topk_e[TK];
__device__ float g_topk_w[TK];
__device__ int   g_counts[NEXP];
__device__ int   g_cursor[NEXP];
__device__ int   g_tile_expert[MAX_TILES];
__device__ int   g_token_list[MAXPAD];
__device__ int   g_pair_slot[TK];
__device__ float g_act[(size_t)MAXPAD * IDIM];
__device__ float g_pairout[(size_t)MAXPAD * HID];

// ---------------- cp.async helpers ----------------
__device__ __forceinline__ void cp_async16(uint32_t dst, const void* src, int sz) {
    asm volatile("cp.async.cg.shared.global [%0], [%1], 16, %2;\n" :: "r"(dst), "l"(src), "r"(sz));
}
__device__ __forceinline__ void cp_commit() { asm volatile("cp.async.commit_group;\n"); }
__device__ __forceinline__ void cp_wait1()  { asm volatile("cp.async.wait_group 1;\n"); }

// ---------------- reset ----------------
__global__ void k_reset() {
    int idx = blockIdx.x * blockDim.x + threadIdx.x;
    if (idx < MAXPAD)    g_token_list[idx] = -1;
    if (idx < MAX_TILES) g_tile_expert[idx] = -1;
    if (idx < NEXP)      g_counts[idx] = 0;
}

// ---------------- router: fp32 logits, softmax, top-8, renorm ----------------
__global__ __launch_bounds__(256) void k_router(
    const float* __restrict__ x, const float* __restrict__ gw,
    float* __restrict__ out_logits, int write_logits)
{
    __shared__ float xs[16 * 64];
    __shared__ float ws[64 * 65];
    __shared__ float lg[16 * 65];

    int tid = threadIdx.x;
    int tok0 = blockIdx.x * 16;
    int e  = tid & 63;
    int tr = tid >> 6;
    float acc0 = 0.f, acc1 = 0.f, acc2 = 0.f, acc3 = 0.f;

    for (int kc = 0; kc < HID; kc += 64) {
        {
            int r  = tid >> 4;
            int c4 = tid & 15;
            float4 v = *(const float4*)(x + (size_t)(tok0 + r) * HID + kc + c4 * 4);
            *(float4*)&xs[r * 64 + c4 * 4] = v;
        }
        #pragma unroll
        for (int p = 0; p < 16; p++) {
            int lin = p * 256 + tid;
            int r = lin >> 6, c = lin & 63;
            ws[r * 65 + c] = gw[(size_t)r * HID + kc + c];
        }
        __syncthreads();
        #pragma unroll 8
        for (int kk = 0; kk < 64; kk++) {
            float wv = ws[e * 65 + kk];
            acc0 += xs[(tr * 4 + 0) * 64 + kk] * wv;
            acc1 += xs[(tr * 4 + 1) * 64 + kk] * wv;
            acc2 += xs[(tr * 4 + 2) * 64 + kk] * wv;
            acc3 += xs[(tr * 4 + 3) * 64 + kk] * wv;
        }
        __syncthreads();
    }
    lg[(tr * 4 + 0) * 65 + e] = acc0;
    lg[(tr * 4 + 1) * 65 + e] = acc1;
    lg[(tr * 4 + 2) * 65 + e] = acc2;
    lg[(tr * 4 + 3) * 65 + e] = acc3;
    __syncthreads();

    if (write_logits) {
        #pragma unroll
        for (int p = 0; p < 4; p++) {
            int lin = p * 256 + tid;
            int t = lin >> 6, ee = lin & 63;
            out_logits[(size_t)(tok0 + t) * NEXP + ee] = lg[t * 65 + ee];
        }
    }

    if (tid < 16) {
        int t = tid;
        float* l = &lg[t * 65];
        float m = -1e30f;
        for (int i = 0; i < NEXP; i++) m = fmaxf(m, l[i]);
        for (int i = 0; i < NEXP; i++) l[i] = expf(l[i] - m);
        int   sel[TOPK];
        float sp[TOPK];
        float wsum = 0.f;
        #pragma unroll
        for (int k = 0; k < TOPK; k++) {
            float bp = -1.f; int be = -1;
            for (int i = 0; i < NEXP; i++)
                if (l[i] > bp) { bp = l[i]; be = i; }
            sel[k] = be; sp[k] = bp; wsum += bp;
            l[be] = -1.f;
        }
        float inv = 1.f / wsum;
        #pragma unroll
        for (int k = 0; k < TOPK; k++) {
            int idx = (tok0 + t) * TOPK + k;
            g_topk_e[idx] = sel[k];
            g_topk_w[idx] = sp[k] * inv;
            atomicAdd(&g_counts[sel[k]], 1);
        }
    }
}

// ---------------- scan ----------------
__global__ void k_scan() {
    if (threadIdx.x == 0 && blockIdx.x == 0) {
        int tile = 0;
        for (int e = 0; e < NEXP; e++) {
            int n = g_counts[e];
            g_cursor[e] = tile * TILE_M;
            int nt = (n + TILE_M - 1) / TILE_M;
            for (int i = 0; i < nt; i++) g_tile_expert[tile + i] = e;
            tile += nt;
        }
    }
}

// ---------------- fill ----------------
__global__ void k_fill() {
    int idx = blockIdx.x * blockDim.x + threadIdx.x;
    if (idx < TK) {
        int e = g_topk_e[idx];
        int p = atomicAdd(&g_cursor[e], 1);
        g_token_list[p] = idx >> 3;
        g_pair_slot[idx] = p;
    }
}

// ---------------- grouped GEMM (tf32 wmma), 128x256 tile, 64x64 warp tile ----
// MODE 0: g_act     = gather(X) @ gate_proj[e]^T   (KD=HID, ND=IDIM)
// MODE 1: g_act     = silu(g_act) * (gather(X) @ up_proj[e]^T)
// MODE 2: g_pairout = g_act @ down_proj[e]^T       (KD=IDIM, ND=HID)
template<int KD, int ND, int MODE>
__global__ __launch_bounds__(256, 1) void k_gemm(
    const float* __restrict__ Aglob, const float* __restrict__ Bglob)
{
    extern __shared__ float sm[];
    __shared__ int toks[TILE_M];

    int tileM = blockIdx.x;
    int eid = g_tile_expert[tileM];
    if (eid < 0) return;
    int slot0 = tileM * TILE_M;
    int n0 = blockIdx.y * TILE_N;
    const float* Bexp = Bglob + (size_t)eid * ND * KD;

    int tid = threadIdx.x;
    if (MODE < 2 && tid < TILE_M) toks[tid] = g_token_list[slot0 + tid];
    __syncthreads();

    uint32_t s_base = (uint32_t)__cvta_generic_to_shared(sm);

    // fill stage s with k-slice k0: A 128x32, B 256x32 (rows padded to 36 floats)
    auto issue = [&](int s, int k0) {
        uint32_t ab = s_base + (uint32_t)(s * ST_FL) * 4;
        uint32_t bb = ab + (uint32_t)A_FL * 4;
        #pragma unroll
        for (int p = 0; p < 4; p++) {                 // A: 1024 float4
            int lin = p * 256 + tid;
            int r = lin >> 3, c = lin & 7;
            uint32_t doff = (uint32_t)(r * AS_STRIDE + c * 4) * 4;
            const float* src; int sz = 16;
            if (MODE < 2) {
                int tk = toks[r];
                src = Aglob + (size_t)(tk < 0 ? 0 : tk) * KD + k0 + c * 4;
                sz = (tk < 0) ? 0 : 16;
            } else {
                src = g_act + (size_t)(slot0 + r) * KD + k0 + c * 4;
            }
            cp_async16(ab + doff, src, sz);
        }
        #pragma unroll
        for (int p = 0; p < 8; p++) {                 // B: 2048 float4
            int lin = p * 256 + tid;
            int r = lin >> 3, c = lin & 7;
            uint32_t doff = (uint32_t)(r * AS_STRIDE + c * 4) * 4;
            cp_async16(bb + doff, Bexp + (size_t)(n0 + r) * KD + k0 + c * 4, 16);
        }
        cp_commit();
    };

    typedef wmma::fragment<wmma::matrix_a, 16, 16, 8, wmma::precision::tf32, wmma::row_major> FragA;
    typedef wmma::fragment<wmma::matrix_b, 16, 16, 8, wmma::precision::tf32, wmma::col_major> FragB;
    typedef wmma::fragment<wmma::accumulator, 16, 16, 8, float> FragC;

    FragC c[4][4];
    #pragma unroll
    for (int i = 0; i < 4; i++)
        #pragma unroll
        for (int j = 0; j < 4; j++)
            wmma::fill_fragment(c[i][j], 0.f);

    int wid = tid >> 5;
    int wm = wid & 1;          // rows wm*64
    int wn = wid >> 1;         // cols wn*64

    const int KT = KD / BK;
    issue(0, 0);
    issue(1, BK);

    for (int kt = 0; kt < KT; kt++) {
        cp_wait1();
        __syncthreads();
        if (kt + 2 < KT) issue((kt + 2) % STAGES, (kt + 2) * BK);

        float* As = sm + (kt % STAGES) * ST_FL;
        float* Bs = As + A_FL;

        #pragma unroll
        for (int kk = 0; kk < BK; kk += 8) {
            FragA a[4];
            FragB b[4];
            #pragma unroll
            for (int i = 0; i < 4; i++)
                wmma::load_matrix_sync(a[i], As + (wm * 64 + i * 16) * AS_STRIDE + kk, AS_STRIDE);
            #pragma unroll
            for (int j = 0; j < 4; j++)
                wmma::load_matrix_sync(b[j], Bs + (wn * 64 + j * 16) * AS_STRIDE + kk, AS_STRIDE);
            #pragma unroll
            for (int i = 0; i < 4; i++)
                #pragma unroll
                for (int t = 0; t < 4; t++)
                    a[i].x[t] = wmma::__float_to_tf32(a[i].x[t]);
            #pragma unroll
            for (int j = 0; j < 4; j++)
                #pragma unroll
                for (int t = 0; t < 4; t++)
                    b[j].x[t] = wmma::__float_to_tf32(b[j].x[t]);
            #pragma unroll
            for (int i = 0; i < 4; i++)
                #pragma unroll
                for (int j = 0; j < 4; j++)
                    wmma::mma_sync(c[i][j], a[i], b[j], c[i][j]);
        }
        __syncthreads();
    }

    if (MODE == 0) {
        #pragma unroll
        for (int i = 0; i < 4; i++)
            #pragma unroll
            for (int j = 0; j < 4; j++)
                wmma::store_matrix_sync(
                    g_act + (size_t)(slot0 + wm * 64 + i * 16) * ND + n0 + wn * 64 + j * 16,
                    c[i][j], ND, wmma::mem_row_major);
    } else if (MODE == 2) {
        #pragma unroll
        for (int i = 0; i < 4; i++)
            #pragma unroll
            for (int j = 0; j < 4; j++)
                wmma::store_matrix_sync(
                    g_pairout + (size_t)(slot0 + wm * 64 + i * 16) * ND + n0 + wn * 64 + j * 16,
                    c[i][j], ND, wmma::mem_row_major);
    } else {
        // MODE 1: stage u tile in smem, fuse act = silu(g)*u
        float* Cs = sm;                   // 128 x CS_STRIDE
        #pragma unroll
        for (int i = 0; i < 4; i++)
            #pragma unroll
            for (int j = 0; j < 4; j++)
                wmma::store_matrix_sync(
                    Cs + (wm * 64 + i * 16) * CS_STRIDE + wn * 64 + j * 16,
                    c[i][j], CS_STRIDE, wmma::mem_row_major);
        __syncthreads();
        #pragma unroll
        for (int p = 0; p < 32; p++) {
            int lin = p * 256 + tid;      // over 8192 float4
            int m = lin >> 6, n4 = lin & 63;
            size_t gi = (size_t)(slot0 + m) * ND + n0 + n4 * 4;
            float4 g = *(float4*)(g_act + gi);
            float4 u = *(float4*)(Cs + m * CS_STRIDE + n4 * 4);
            float4 o;
            o.x = (g.x / (1.f + expf(-g.x))) * u.x;
            o.y = (g.y / (1.f + expf(-g.y))) * u.y;
            o.z = (g.z / (1.f + expf(-g.z))) * u.z;
            o.w = (g.w / (1.f + expf(-g.w))) * u.w;
            *(float4*)(g_act + gi) = o;
        }
    }
}

// ---------------- combine ----------------
__global__ __launch_bounds__(256) void k_combine(float* __restrict__ out) {
    size_t idx = (size_t)blockIdx.x * 256 + threadIdx.x;   // over T*H/4
    int t  = (int)(idx >> 9);
    int h4 = (int)(idx & 511);
    float4 s = make_float4(0.f, 0.f, 0.f, 0.f);
    #pragma unroll
    for (int k = 0; k < TOPK; k++) {
        int pi = t * TOPK + k;
        int p = g_pair_slot[pi];
        float w = g_topk_w[pi];
        float4 v = *(const float4*)(g_pairout + (size_t)p * HID + h4 * 4);
        s.x += w * v.x; s.y += w * v.y; s.z += w * v.z; s.w += w * v.w;
    }
    *(float4*)(out + idx * 4) = s;
}

// ---------------- launch ----------------
extern "C" void kernel_launch(void* const* d_in, const int* in_sizes, int n_in,
                              void* d_out, int out_size) {
    const float* x  = (const float*)d_in[0];
    const float* gw = (const float*)d_in[1];
    const float* gp = (const float*)d_in[2];
    const float* up = (const float*)d_in[3];
    const float* dp = (const float*)d_in[4];
    float* out = (float*)d_out;
    float* out_logits = out + (size_t)T_TOK * HID;
    int write_logits = (out_size >= T_TOK * HID + T_TOK * NEXP) ? 1 : 0;

    cudaFuncSetAttribute(k_gemm<HID, IDIM, 0>,
                         cudaFuncAttributeMaxDynamicSharedMemorySize, GEMM_SMEM);
    cudaFuncSetAttribute(k_gemm<HID, IDIM, 1>,
                         cudaFuncAttributeMaxDynamicSharedMemorySize, GEMM_SMEM);
    cudaFuncSetAttribute(k_gemm<IDIM, HID, 2>,
                         cudaFuncAttributeMaxDynamicSharedMemorySize, GEMM_SMEM);

    k_reset<<<(MAXPAD + 255) / 256, 256>>>();
    k_router<<<T_TOK / 16, 256>>>(x, gw, out_logits, write_logits);
    k_scan<<<1, 32>>>();
    k_fill<<<(TK + 255) / 256, 256>>>();

    k_gemm<HID, IDIM, 0><<<dim3(MAX_TILES, IDIM / TILE_N), 256, GEMM_SMEM>>>(x, gp);
    k_gemm<HID, IDIM, 1><<<dim3(MAX_TILES, IDIM / TILE_N), 256, GEMM_SMEM>>>(x, up);
    k_gemm<IDIM, HID, 2><<<dim3(MAX_TILES, HID / TILE_N), 256, GEMM_SMEM>>>(x, dp);

    k_combine<<<T_TOK * HID / 4 / 256, 256>>>(out);
}

// round 5
// speedup vs baseline: 1.2781x; 1.0237x over previous
#include <cuda_runtime.h>
#include <cuda_bf16.h>
#include <mma.h>
#include <math.h>
#include <stdint.h>

using namespace nvcuda;

// Problem constants
#define T_TOK 8192
#define HID   2048
#define NEXP  64
#define IDIM  768
#define TOPK  8
#define TK    (T_TOK*TOPK)               // 65536 pairs
#define TILE_M 128
#define MAX_TILES ((TK/TILE_M) + NEXP)   // 576
#define MAXPAD (MAX_TILES*TILE_M)        // 73728
#define WELEM  ((size_t)NEXP*IDIM*HID)   // 100663296 elements per weight tensor

// GEMM geometry: block 128x256, warp 64x64 (2x4 warps), BK=32, 4-stage cp.async
#define BK       32
#define TILE_N   256
#define AS_STRIDE 36                      // 32 + 4 pad floats
#define A_FL     (128*AS_STRIDE)          // 4608 floats
#define B_FL     (256*AS_STRIDE)          // 9216 floats
#define ST_FL    (A_FL + B_FL)            // 13824 floats per stage
#define STAGES   4
#define GEMM_SMEM (STAGES*ST_FL*4)        // 221184 B
#define CS_STRIDE 260                     // epilogue staging stride

// ---------------- scratch ----------------
__device__ int   g_topk_e[TK];
__device__ float g_topk_w[TK];
__device__ int   g_counts[NEXP];
__device__ int   g_cursor[NEXP];
__device__ int   g_tile_expert[MAX_TILES];
__device__ int   g_token_list[MAXPAD];
__device__ int   g_pair_slot[TK];
__device__ float g_act[(size_t)MAXPAD * IDIM];
__device__ float g_pairout[(size_t)MAXPAD * HID];
// tf32-pre-rounded operand copies
__device__ float g_xr[(size_t)T_TOK * HID];
__device__ float g_gpr[WELEM];
__device__ float g_upr[WELEM];
__device__ float g_dpr[WELEM];

// ---------------- cp.async helpers ----------------
__device__ __forceinline__ void cp_async16(uint32_t dst, const void* src, int sz) {
    asm volatile("cp.async.cg.shared.global [%0], [%1], 16, %2;\n" :: "r"(dst), "l"(src), "r"(sz));
}
__device__ __forceinline__ void cp_commit() { asm volatile("cp.async.commit_group;\n"); }
__device__ __forceinline__ void cp_wait2()  { asm volatile("cp.async.wait_group 2;\n"); }

// ---------------- tf32 pre-round (RN, same op as wmma::__float_to_tf32) ----------
__global__ __launch_bounds__(256) void k_round(const float4* __restrict__ s,
                                               float4* __restrict__ d, int n4) {
    int i = blockIdx.x * 256 + threadIdx.x;
    if (i < n4) {
        float4 v = s[i];
        v.x = wmma::__float_to_tf32(v.x);
        v.y = wmma::__float_to_tf32(v.y);
        v.z = wmma::__float_to_tf32(v.z);
        v.w = wmma::__float_to_tf32(v.w);
        d[i] = v;
    }
}

// ---------------- reset ----------------
__global__ void k_reset() {
    int idx = blockIdx.x * blockDim.x + threadIdx.x;
    if (idx < MAXPAD)    g_token_list[idx] = -1;
    if (idx < MAX_TILES) g_tile_expert[idx] = -1;
    if (idx < NEXP)      g_counts[idx] = 0;
}

// ---------------- router: fp32 logits, softmax, top-8, renorm ----------------
__global__ __launch_bounds__(256) void k_router(
    const float* __restrict__ x, const float* __restrict__ gw,
    float* __restrict__ out_logits, int write_logits)
{
    __shared__ float xs[16 * 64];
    __shared__ float ws[64 * 65];
    __shared__ float lg[16 * 65];

    int tid = threadIdx.x;
    int tok0 = blockIdx.x * 16;
    int e  = tid & 63;
    int tr = tid >> 6;
    float acc0 = 0.f, acc1 = 0.f, acc2 = 0.f, acc3 = 0.f;

    for (int kc = 0; kc < HID; kc += 64) {
        {
            int r  = tid >> 4;
            int c4 = tid & 15;
            float4 v = *(const float4*)(x + (size_t)(tok0 + r) * HID + kc + c4 * 4);
            *(float4*)&xs[r * 64 + c4 * 4] = v;
        }
        #pragma unroll
        for (int p = 0; p < 16; p++) {
            int lin = p * 256 + tid;
            int r = lin >> 6, c = lin & 63;
            ws[r * 65 + c] = gw[(size_t)r * HID + kc + c];
        }
        __syncthreads();
        #pragma unroll 8
        for (int kk = 0; kk < 64; kk++) {
            float wv = ws[e * 65 + kk];
            acc0 += xs[(tr * 4 + 0) * 64 + kk] * wv;
            acc1 += xs[(tr * 4 + 1) * 64 + kk] * wv;
            acc2 += xs[(tr * 4 + 2) * 64 + kk] * wv;
            acc3 += xs[(tr * 4 + 3) * 64 + kk] * wv;
        }
        __syncthreads();
    }
    lg[(tr * 4 + 0) * 65 + e] = acc0;
    lg[(tr * 4 + 1) * 65 + e] = acc1;
    lg[(tr * 4 + 2) * 65 + e] = acc2;
    lg[(tr * 4 + 3) * 65 + e] = acc3;
    __syncthreads();

    if (write_logits) {
        #pragma unroll
        for (int p = 0; p < 4; p++) {
            int lin = p * 256 + tid;
            int t = lin >> 6, ee = lin & 63;
            out_logits[(size_t)(tok0 + t) * NEXP + ee] = lg[t * 65 + ee];
        }
    }

    if (tid < 16) {
        int t = tid;
        float* l = &lg[t * 65];
        float m = -1e30f;
        for (int i = 0; i < NEXP; i++) m = fmaxf(m, l[i]);
        for (int i = 0; i < NEXP; i++) l[i] = expf(l[i] - m);
        int   sel[TOPK];
        float sp[TOPK];
        float wsum = 0.f;
        #pragma unroll
        for (int k = 0; k < TOPK; k++) {
            float bp = -1.f; int be = -1;
            for (int i = 0; i < NEXP; i++)
                if (l[i] > bp) { bp = l[i]; be = i; }
            sel[k] = be; sp[k] = bp; wsum += bp;
            l[be] = -1.f;
        }
        float inv = 1.f / wsum;
        #pragma unroll
        for (int k = 0; k < TOPK; k++) {
            int idx = (tok0 + t) * TOPK + k;
            g_topk_e[idx] = sel[k];
            g_topk_w[idx] = sp[k] * inv;
            atomicAdd(&g_counts[sel[k]], 1);
        }
    }
}

// ---------------- scan ----------------
__global__ void k_scan() {
    if (threadIdx.x == 0 && blockIdx.x == 0) {
        int tile = 0;
        for (int e = 0; e < NEXP; e++) {
            int n = g_counts[e];
            g_cursor[e] = tile * TILE_M;
            int nt = (n + TILE_M - 1) / TILE_M;
            for (int i = 0; i < nt; i++) g_tile_expert[tile + i] = e;
            tile += nt;
        }
    }
}

// ---------------- fill ----------------
__global__ void k_fill() {
    int idx = blockIdx.x * blockDim.x + threadIdx.x;
    if (idx < TK) {
        int e = g_topk_e[idx];
        int p = atomicAdd(&g_cursor[e], 1);
        g_token_list[p] = idx >> 3;
        g_pair_slot[idx] = p;
    }
}

// ---------------- grouped GEMM (tf32 wmma, pre-rounded inputs, no in-loop CVT) ----
// MODE 0: g_act     = gather(Xr) @ gpr[e]^T   (KD=HID, ND=IDIM)
// MODE 1: g_act     = silu(g_act) * (gather(Xr) @ upr[e]^T), result tf32-rounded
// MODE 2: g_pairout = g_act @ dpr[e]^T        (KD=IDIM, ND=HID)
template<int KD, int ND, int MODE>
__global__ __launch_bounds__(256, 1) void k_gemm(
    const float* __restrict__ Aglob, const float* __restrict__ Bglob)
{
    extern __shared__ float sm[];
    __shared__ int toks[TILE_M];

    int tileM = blockIdx.x;
    int eid = g_tile_expert[tileM];
    if (eid < 0) return;
    int slot0 = tileM * TILE_M;
    int n0 = blockIdx.y * TILE_N;
    const float* Bexp = Bglob + (size_t)eid * ND * KD;

    int tid = threadIdx.x;
    if (MODE < 2 && tid < TILE_M) toks[tid] = g_token_list[slot0 + tid];
    __syncthreads();

    uint32_t s_base = (uint32_t)__cvta_generic_to_shared(sm);

    auto issue = [&](int s, int k0) {
        uint32_t ab = s_base + (uint32_t)(s * ST_FL) * 4;
        uint32_t bb = ab + (uint32_t)A_FL * 4;
        #pragma unroll
        for (int p = 0; p < 4; p++) {                 // A: 1024 float4
            int lin = p * 256 + tid;
            int r = lin >> 3, c = lin & 7;
            uint32_t doff = (uint32_t)(r * AS_STRIDE + c * 4) * 4;
            const float* src; int sz = 16;
            if (MODE < 2) {
                int tk = toks[r];
                src = Aglob + (size_t)(tk < 0 ? 0 : tk) * KD + k0 + c * 4;
                sz = (tk < 0) ? 0 : 16;
            } else {
                src = g_act + (size_t)(slot0 + r) * KD + k0 + c * 4;
            }
            cp_async16(ab + doff, src, sz);
        }
        #pragma unroll
        for (int p = 0; p < 8; p++) {                 // B: 2048 float4
            int lin = p * 256 + tid;
            int r = lin >> 3, c = lin & 7;
            uint32_t doff = (uint32_t)(r * AS_STRIDE + c * 4) * 4;
            cp_async16(bb + doff, Bexp + (size_t)(n0 + r) * KD + k0 + c * 4, 16);
        }
        cp_commit();
    };

    typedef wmma::fragment<wmma::matrix_a, 16, 16, 8, wmma::precision::tf32, wmma::row_major> FragA;
    typedef wmma::fragment<wmma::matrix_b, 16, 16, 8, wmma::precision::tf32, wmma::col_major> FragB;
    typedef wmma::fragment<wmma::accumulator, 16, 16, 8, float> FragC;

    FragC c[4][4];
    #pragma unroll
    for (int i = 0; i < 4; i++)
        #pragma unroll
        for (int j = 0; j < 4; j++)
            wmma::fill_fragment(c[i][j], 0.f);

    int wid = tid >> 5;
    int wm = wid & 1;          // rows wm*64
    int wn = wid >> 1;         // cols wn*64

    const int KT = KD / BK;
    issue(0, 0);
    issue(1, BK);
    issue(2, 2 * BK);

    for (int kt = 0; kt < KT; kt++) {
        cp_wait2();
        __syncthreads();
        if (kt + 3 < KT) issue((kt + 3) % STAGES, (kt + 3) * BK);

        float* As = sm + (kt % STAGES) * ST_FL;
        float* Bs = As + A_FL;

        #pragma unroll
        for (int kk = 0; kk < BK; kk += 8) {
            FragA a[4];
            FragB b[4];
            #pragma unroll
            for (int i = 0; i < 4; i++)
                wmma::load_matrix_sync(a[i], As + (wm * 64 + i * 16) * AS_STRIDE + kk, AS_STRIDE);
            #pragma unroll
            for (int j = 0; j < 4; j++)
                wmma::load_matrix_sync(b[j], Bs + (wn * 64 + j * 16) * AS_STRIDE + kk, AS_STRIDE);
            // NOTE: no CVT — operands were pre-rounded to tf32 in gmem.
            #pragma unroll
            for (int i = 0; i < 4; i++)
                #pragma unroll
                for (int j = 0; j < 4; j++)
                    wmma::mma_sync(c[i][j], a[i], b[j], c[i][j]);
        }
        __syncthreads();
    }

    if (MODE == 0) {
        #pragma unroll
        for (int i = 0; i < 4; i++)
            #pragma unroll
            for (int j = 0; j < 4; j++)
                wmma::store_matrix_sync(
                    g_act + (size_t)(slot0 + wm * 64 + i * 16) * ND + n0 + wn * 64 + j * 16,
                    c[i][j], ND, wmma::mem_row_major);
    } else if (MODE == 2) {
        #pragma unroll
        for (int i = 0; i < 4; i++)
            #pragma unroll
            for (int j = 0; j < 4; j++)
                wmma::store_matrix_sync(
                    g_pairout + (size_t)(slot0 + wm * 64 + i * 16) * ND + n0 + wn * 64 + j * 16,
                    c[i][j], ND, wmma::mem_row_major);
    } else {
        // MODE 1: stage u tile in smem, fuse act = tf32(silu(g)*u)
        float* Cs = sm;                   // 128 x CS_STRIDE
        #pragma unroll
        for (int i = 0; i < 4; i++)
            #pragma unroll
            for (int j = 0; j < 4; j++)
                wmma::store_matrix_sync(
                    Cs + (wm * 64 + i * 16) * CS_STRIDE + wn * 64 + j * 16,
                    c[i][j], CS_STRIDE, wmma::mem_row_major);
        __syncthreads();
        #pragma unroll
        for (int p = 0; p < 32; p++) {
            int lin = p * 256 + tid;      // over 8192 float4
            int m = lin >> 6, n4 = lin & 63;
            size_t gi = (size_t)(slot0 + m) * ND + n0 + n4 * 4;
            float4 g = *(float4*)(g_act + gi);
            float4 u = *(float4*)(Cs + m * CS_STRIDE + n4 * 4);
            float4 o;
            o.x = wmma::__float_to_tf32((g.x / (1.f + expf(-g.x))) * u.x);
            o.y = wmma::__float_to_tf32((g.y / (1.f + expf(-g.y))) * u.y);
            o.z = wmma::__float_to_tf32((g.z / (1.f + expf(-g.z))) * u.z);
            o.w = wmma::__float_to_tf32((g.w / (1.f + expf(-g.w))) * u.w);
            *(float4*)(g_act + gi) = o;
        }
    }
}

// ---------------- combine ----------------
__global__ __launch_bounds__(256) void k_combine(float* __restrict__ out) {
    size_t idx = (size_t)blockIdx.x * 256 + threadIdx.x;   // over T*H/4
    int t  = (int)(idx >> 9);
    int h4 = (int)(idx & 511);
    float4 s = make_float4(0.f, 0.f, 0.f, 0.f);
    #pragma unroll
    for (int k = 0; k < TOPK; k++) {
        int pi = t * TOPK + k;
        int p = g_pair_slot[pi];
        float w = g_topk_w[pi];
        float4 v = *(const float4*)(g_pairout + (size_t)p * HID + h4 * 4);
        s.x += w * v.x; s.y += w * v.y; s.z += w * v.z; s.w += w * v.w;
    }
    *(float4*)(out + idx * 4) = s;
}

// ---------------- launch ----------------
extern "C" void kernel_launch(void* const* d_in, const int* in_sizes, int n_in,
                              void* d_out, int out_size) {
    const float* x  = (const float*)d_in[0];
    const float* gw = (const float*)d_in[1];
    const float* gp = (const float*)d_in[2];
    const float* up = (const float*)d_in[3];
    const float* dp = (const float*)d_in[4];
    float* out = (float*)d_out;
    float* out_logits = out + (size_t)T_TOK * HID;
    int write_logits = (out_size >= T_TOK * HID + T_TOK * NEXP) ? 1 : 0;

    cudaFuncSetAttribute(k_gemm<HID, IDIM, 0>,
                         cudaFuncAttributeMaxDynamicSharedMemorySize, GEMM_SMEM);
    cudaFuncSetAttribute(k_gemm<HID, IDIM, 1>,
                         cudaFuncAttributeMaxDynamicSharedMemorySize, GEMM_SMEM);
    cudaFuncSetAttribute(k_gemm<IDIM, HID, 2>,
                         cudaFuncAttributeMaxDynamicSharedMemorySize, GEMM_SMEM);

    // resolve scratch addresses (device symbols)
    float *xr_p, *gpr_p, *upr_p, *dpr_p;
    cudaGetSymbolAddress((void**)&xr_p,  g_xr);
    cudaGetSymbolAddress((void**)&gpr_p, g_gpr);
    cudaGetSymbolAddress((void**)&upr_p, g_upr);
    cudaGetSymbolAddress((void**)&dpr_p, g_dpr);

    const int W4 = (int)(WELEM / 4);                   // 25165824
    const int X4 = T_TOK * HID / 4;                    // 4194304

    k_reset<<<(MAXPAD + 255) / 256, 256>>>();
    k_router<<<T_TOK / 16, 256>>>(x, gw, out_logits, write_logits);
    k_scan<<<1, 32>>>();
    k_fill<<<(TK + 255) / 256, 256>>>();

    // pre-round all GEMM operands to tf32 (RN) once
    k_round<<<(X4 + 255) / 256, 256>>>((const float4*)x,  (float4*)xr_p,  X4);
    k_round<<<(W4 + 255) / 256, 256>>>((const float4*)gp, (float4*)gpr_p, W4);
    k_round<<<(W4 + 255) / 256, 256>>>((const float4*)up, (float4*)upr_p, W4);
    k_round<<<(W4 + 255) / 256, 256>>>((const float4*)dp, (float4*)dpr_p, W4);

    k_gemm<HID, IDIM, 0><<<dim3(MAX_TILES, IDIM / TILE_N), 256, GEMM_SMEM>>>(xr_p, gpr_p);
    k_gemm<HID, IDIM, 1><<<dim3(MAX_TILES, IDIM / TILE_N), 256, GEMM_SMEM>>>(xr_p, upr_p);
    k_gemm<IDIM, HID, 2><<<dim3(MAX_TILES, HID / TILE_N), 256, GEMM_SMEM>>>(xr_p, dpr_p);

    k_combine<<<T_TOK * HID / 4 / 256, 256>>>(out);
}

// round 6
// speedup vs baseline: 3.8901x; 3.0436x over previous
#include <cuda_runtime.h>
#include <cuda_fp16.h>
#include <mma.h>
#include <math.h>
#include <stdint.h>

using namespace nvcuda;

// Problem constants
#define T_TOK 8192
#define HID   2048
#define NEXP  64
#define IDIM  768
#define TOPK  8
#define TK    (T_TOK*TOPK)               // 65536 pairs
#define TILE_M 128
#define MAX_TILES ((TK/TILE_M) + NEXP)   // 576
#define MAXPAD (MAX_TILES*TILE_M)        // 73728
#define WELEM  ((size_t)NEXP*IDIM*HID)   // 100663296 per weight tensor

// GEMM geometry: block 128x256, warp 64x64 (2x4 warps), BK=64 halfs, 4-stage cp.async
#define BK       64
#define TILE_N   256
#define HS_STRIDE 72                      // 64 + 8 pad halfs (144B rows)
#define A_HL     (128*HS_STRIDE)          // 9216 halfs
#define B_HL     (256*HS_STRIDE)          // 18432 halfs
#define ST_HL    (A_HL + B_HL)            // 27648 halfs (55296 B) per stage
#define STAGES   4
#define GEMM_SMEM (STAGES*ST_HL*2)        // 221184 B
#define CS_STRIDE 260                     // fp32 epilogue staging stride

// ---------------- scratch ----------------
__device__ int    g_topk_e[TK];
__device__ float  g_topk_w[TK];
__device__ int    g_counts[NEXP];
__device__ int    g_cursor[NEXP];
__device__ int    g_tile_expert[MAX_TILES];
__device__ int    g_token_list[MAXPAD];
__device__ int    g_pair_slot[TK];
__device__ float  g_act[(size_t)MAXPAD * IDIM];     // fp32 gate output
__device__ __half g_acth[(size_t)MAXPAD * IDIM];    // fp16 act = silu(g)*u
__device__ float  g_pairout[(size_t)MAXPAD * HID];
// fp16 operand copies
__device__ __half g_xh[(size_t)T_TOK * HID];
__device__ __half g_gph[WELEM];
__device__ __half g_uph[WELEM];
__device__ __half g_dph[WELEM];

// ---------------- cp.async helpers ----------------
__device__ __forceinline__ void cp_async16(uint32_t dst, const void* src, int sz) {
    asm volatile("cp.async.cg.shared.global [%0], [%1], 16, %2;\n" :: "r"(dst), "l"(src), "r"(sz));
}
__device__ __forceinline__ void cp_commit() { asm volatile("cp.async.commit_group;\n"); }
__device__ __forceinline__ void cp_wait2()  { asm volatile("cp.async.wait_group 2;\n"); }

// ---------------- fp32 -> fp16 conversion (8 elems/thread) ----------------
__global__ __launch_bounds__(256) void k_cvt(const float4* __restrict__ s,
                                             uint4* __restrict__ d, size_t n8) {
    size_t i = (size_t)blockIdx.x * 256 + threadIdx.x;
    if (i < n8) {
        float4 a = s[2 * i], b = s[2 * i + 1];
        __half2 h0 = __floats2half2_rn(a.x, a.y);
        __half2 h1 = __floats2half2_rn(a.z, a.w);
        __half2 h2 = __floats2half2_rn(b.x, b.y);
        __half2 h3 = __floats2half2_rn(b.z, b.w);
        uint4 o;
        o.x = *(unsigned*)&h0; o.y = *(unsigned*)&h1;
        o.z = *(unsigned*)&h2; o.w = *(unsigned*)&h3;
        d[i] = o;
    }
}

// ---------------- reset ----------------
__global__ void k_reset() {
    int idx = blockIdx.x * blockDim.x + threadIdx.x;
    if (idx < MAXPAD)    g_token_list[idx] = -1;
    if (idx < MAX_TILES) g_tile_expert[idx] = -1;
    if (idx < NEXP)      g_counts[idx] = 0;
}

// ---------------- router: fp32 logits, softmax, top-8, renorm ----------------
__global__ __launch_bounds__(256) void k_router(
    const float* __restrict__ x, const float* __restrict__ gw,
    float* __restrict__ out_logits, int write_logits)
{
    __shared__ float xs[16 * 64];
    __shared__ float ws[64 * 65];
    __shared__ float lg[16 * 65];

    int tid = threadIdx.x;
    int tok0 = blockIdx.x * 16;
    int e  = tid & 63;
    int tr = tid >> 6;
    float acc0 = 0.f, acc1 = 0.f, acc2 = 0.f, acc3 = 0.f;

    for (int kc = 0; kc < HID; kc += 64) {
        {
            int r  = tid >> 4;
            int c4 = tid & 15;
            float4 v = *(const float4*)(x + (size_t)(tok0 + r) * HID + kc + c4 * 4);
            *(float4*)&xs[r * 64 + c4 * 4] = v;
        }
        #pragma unroll
        for (int p = 0; p < 16; p++) {
            int lin = p * 256 + tid;
            int r = lin >> 6, c = lin & 63;
            ws[r * 65 + c] = gw[(size_t)r * HID + kc + c];
        }
        __syncthreads();
        #pragma unroll 8
        for (int kk = 0; kk < 64; kk++) {
            float wv = ws[e * 65 + kk];
            acc0 += xs[(tr * 4 + 0) * 64 + kk] * wv;
            acc1 += xs[(tr * 4 + 1) * 64 + kk] * wv;
            acc2 += xs[(tr * 4 + 2) * 64 + kk] * wv;
            acc3 += xs[(tr * 4 + 3) * 64 + kk] * wv;
        }
        __syncthreads();
    }
    lg[(tr * 4 + 0) * 65 + e] = acc0;
    lg[(tr * 4 + 1) * 65 + e] = acc1;
    lg[(tr * 4 + 2) * 65 + e] = acc2;
    lg[(tr * 4 + 3) * 65 + e] = acc3;
    __syncthreads();

    if (write_logits) {
        #pragma unroll
        for (int p = 0; p < 4; p++) {
            int lin = p * 256 + tid;
            int t = lin >> 6, ee = lin & 63;
            out_logits[(size_t)(tok0 + t) * NEXP + ee] = lg[t * 65 + ee];
        }
    }

    if (tid < 16) {
        int t = tid;
        float* l = &lg[t * 65];
        float m = -1e30f;
        for (int i = 0; i < NEXP; i++) m = fmaxf(m, l[i]);
        for (int i = 0; i < NEXP; i++) l[i] = expf(l[i] - m);
        int   sel[TOPK];
        float sp[TOPK];
        float wsum = 0.f;
        #pragma unroll
        for (int k = 0; k < TOPK; k++) {
            float bp = -1.f; int be = -1;
            for (int i = 0; i < NEXP; i++)
                if (l[i] > bp) { bp = l[i]; be = i; }
            sel[k] = be; sp[k] = bp; wsum += bp;
            l[be] = -1.f;
        }
        float inv = 1.f / wsum;
        #pragma unroll
        for (int k = 0; k < TOPK; k++) {
            int idx = (tok0 + t) * TOPK + k;
            g_topk_e[idx] = sel[k];
            g_topk_w[idx] = sp[k] * inv;
            atomicAdd(&g_counts[sel[k]], 1);
        }
    }
}

// ---------------- scan ----------------
__global__ void k_scan() {
    if (threadIdx.x == 0 && blockIdx.x == 0) {
        int tile = 0;
        for (int e = 0; e < NEXP; e++) {
            int n = g_counts[e];
            g_cursor[e] = tile * TILE_M;
            int nt = (n + TILE_M - 1) / TILE_M;
            for (int i = 0; i < nt; i++) g_tile_expert[tile + i] = e;
            tile += nt;
        }
    }
}

// ---------------- fill ----------------
__global__ void k_fill() {
    int idx = blockIdx.x * blockDim.x + threadIdx.x;
    if (idx < TK) {
        int e = g_topk_e[idx];
        int p = atomicAdd(&g_cursor[e], 1);
        g_token_list[p] = idx >> 3;
        g_pair_slot[idx] = p;
    }
}

// ---------------- grouped GEMM (fp16 wmma m16n16k16, fp32 accum) ----
// MODE 0: g_act(fp32)  = gather(xh) @ gph[e]^T    (KD=HID, ND=IDIM)
// MODE 1: g_acth(fp16) = silu(g_act) * (gather(xh) @ uph[e]^T)
// MODE 2: g_pairout    = g_acth @ dph[e]^T        (KD=IDIM, ND=HID)
template<int KD, int ND, int MODE>
__global__ __launch_bounds__(256, 1) void k_gemm(
    const __half* __restrict__ Aglob, const __half* __restrict__ Bglob)
{
    extern __shared__ __half smh[];
    __shared__ int toks[TILE_M];

    int tileM = blockIdx.x;
    int eid = g_tile_expert[tileM];
    if (eid < 0) return;
    int slot0 = tileM * TILE_M;
    int n0 = blockIdx.y * TILE_N;
    const __half* Bexp = Bglob + (size_t)eid * ND * KD;

    int tid = threadIdx.x;
    if (MODE < 2 && tid < TILE_M) toks[tid] = g_token_list[slot0 + tid];
    __syncthreads();

    uint32_t s_base = (uint32_t)__cvta_generic_to_shared(smh);

    // fill stage s with k-slice k0: A 128x64h, B 256x64h (rows padded to 72h)
    auto issue = [&](int s, int k0) {
        uint32_t ab = s_base + (uint32_t)(s * ST_HL) * 2;
        uint32_t bb = ab + (uint32_t)A_HL * 2;
        #pragma unroll
        for (int p = 0; p < 4; p++) {                 // A: 1024 chunks of 16B
            int lin = p * 256 + tid;
            int r = lin >> 3, c = lin & 7;
            uint32_t doff = (uint32_t)(r * HS_STRIDE + c * 8) * 2;
            const __half* src; int sz = 16;
            if (MODE < 2) {
                int tk = toks[r];
                src = Aglob + (size_t)(tk < 0 ? 0 : tk) * KD + k0 + c * 8;
                sz = (tk < 0) ? 0 : 16;
            } else {
                src = g_acth + (size_t)(slot0 + r) * KD + k0 + c * 8;
            }
            cp_async16(ab + doff, src, sz);
        }
        #pragma unroll
        for (int p = 0; p < 8; p++) {                 // B: 2048 chunks of 16B
            int lin = p * 256 + tid;
            int r = lin >> 3, c = lin & 7;
            uint32_t doff = (uint32_t)(r * HS_STRIDE + c * 8) * 2;
            cp_async16(bb + doff, Bexp + (size_t)(n0 + r) * KD + k0 + c * 8, 16);
        }
        cp_commit();
    };

    typedef wmma::fragment<wmma::matrix_a, 16, 16, 16, __half, wmma::row_major> FragA;
    typedef wmma::fragment<wmma::matrix_b, 16, 16, 16, __half, wmma::col_major> FragB;
    typedef wmma::fragment<wmma::accumulator, 16, 16, 16, float> FragC;

    FragC c[4][4];
    #pragma unroll
    for (int i = 0; i < 4; i++)
        #pragma unroll
        for (int j = 0; j < 4; j++)
            wmma::fill_fragment(c[i][j], 0.f);

    int wid = tid >> 5;
    int wm = wid & 1;          // rows wm*64
    int wn = wid >> 1;         // cols wn*64

    const int KT = KD / BK;    // 32 (gate/up) or 12 (down)
    issue(0, 0);
    issue(1, BK);
    issue(2, 2 * BK);

    for (int kt = 0; kt < KT; kt++) {
        cp_wait2();
        __syncthreads();
        if (kt + 3 < KT) issue((kt + 3) % STAGES, (kt + 3) * BK);

        __half* As = smh + (kt % STAGES) * ST_HL;
        __half* Bs = As + A_HL;

        #pragma unroll
        for (int kk = 0; kk < BK; kk += 16) {
            FragA a[4];
            FragB b[4];
            #pragma unroll
            for (int i = 0; i < 4; i++)
                wmma::load_matrix_sync(a[i], As + (wm * 64 + i * 16) * HS_STRIDE + kk, HS_STRIDE);
            #pragma unroll
            for (int j = 0; j < 4; j++)
                wmma::load_matrix_sync(b[j], Bs + (wn * 64 + j * 16) * HS_STRIDE + kk, HS_STRIDE);
            #pragma unroll
            for (int i = 0; i < 4; i++)
                #pragma unroll
                for (int j = 0; j < 4; j++)
                    wmma::mma_sync(c[i][j], a[i], b[j], c[i][j]);
        }
        __syncthreads();
    }

    if (MODE == 0) {
        #pragma unroll
        for (int i = 0; i < 4; i++)
            #pragma unroll
            for (int j = 0; j < 4; j++)
                wmma::store_matrix_sync(
                    g_act + (size_t)(slot0 + wm * 64 + i * 16) * ND + n0 + wn * 64 + j * 16,
                    c[i][j], ND, wmma::mem_row_major);
    } else if (MODE == 2) {
        #pragma unroll
        for (int i = 0; i < 4; i++)
            #pragma unroll
            for (int j = 0; j < 4; j++)
                wmma::store_matrix_sync(
                    g_pairout + (size_t)(slot0 + wm * 64 + i * 16) * ND + n0 + wn * 64 + j * 16,
                    c[i][j], ND, wmma::mem_row_major);
    } else {
        // MODE 1: stage u tile (fp32) in smem, fuse act = fp16(silu(g)*u)
        float* Cs = (float*)smh;          // 128 x CS_STRIDE fp32 (133120 B <= smem)
        #pragma unroll
        for (int i = 0; i < 4; i++)
            #pragma unroll
            for (int j = 0; j < 4; j++)
                wmma::store_matrix_sync(
                    Cs + (wm * 64 + i * 16) * CS_STRIDE + wn * 64 + j * 16,
                    c[i][j], CS_STRIDE, wmma::mem_row_major);
        __syncthreads();
        #pragma unroll
        for (int p = 0; p < 32; p++) {
            int lin = p * 256 + tid;      // over 8192 groups of 4
            int m = lin >> 6, n4 = lin & 63;
            size_t gi = (size_t)(slot0 + m) * ND + n0 + n4 * 4;
            float4 g = *(float4*)(g_act + gi);
            float4 u = *(float4*)(Cs + m * CS_STRIDE + n4 * 4);
            float ax = (g.x / (1.f + expf(-g.x))) * u.x;
            float ay = (g.y / (1.f + expf(-g.y))) * u.y;
            float az = (g.z / (1.f + expf(-g.z))) * u.z;
            float aw = (g.w / (1.f + expf(-g.w))) * u.w;
            __half2 h0 = __floats2half2_rn(ax, ay);
            __half2 h1 = __floats2half2_rn(az, aw);
            uint2 o; o.x = *(unsigned*)&h0; o.y = *(unsigned*)&h1;
            *(uint2*)(g_acth + gi) = o;
        }
    }
}

// ---------------- combine ----------------
__global__ __launch_bounds__(256) void k_combine(float* __restrict__ out) {
    size_t idx = (size_t)blockIdx.x * 256 + threadIdx.x;   // over T*H/4
    int t  = (int)(idx >> 9);
    int h4 = (int)(idx & 511);
    float4 s = make_float4(0.f, 0.f, 0.f, 0.f);
    #pragma unroll
    for (int k = 0; k < TOPK; k++) {
        int pi = t * TOPK + k;
        int p = g_pair_slot[pi];
        float w = g_topk_w[pi];
        float4 v = *(const float4*)(g_pairout + (size_t)p * HID + h4 * 4);
        s.x += w * v.x; s.y += w * v.y; s.z += w * v.z; s.w += w * v.w;
    }
    *(float4*)(out + idx * 4) = s;
}

// ---------------- launch ----------------
extern "C" void kernel_launch(void* const* d_in, const int* in_sizes, int n_in,
                              void* d_out, int out_size) {
    const float* x  = (const float*)d_in[0];
    const float* gw = (const float*)d_in[1];
    const float* gp = (const float*)d_in[2];
    const float* up = (const float*)d_in[3];
    const float* dp = (const float*)d_in[4];
    float* out = (float*)d_out;
    float* out_logits = out + (size_t)T_TOK * HID;
    int write_logits = (out_size >= T_TOK * HID + T_TOK * NEXP) ? 1 : 0;

    cudaFuncSetAttribute(k_gemm<HID, IDIM, 0>,
                         cudaFuncAttributeMaxDynamicSharedMemorySize, GEMM_SMEM);
    cudaFuncSetAttribute(k_gemm<HID, IDIM, 1>,
                         cudaFuncAttributeMaxDynamicSharedMemorySize, GEMM_SMEM);
    cudaFuncSetAttribute(k_gemm<IDIM, HID, 2>,
                         cudaFuncAttributeMaxDynamicSharedMemorySize, GEMM_SMEM);

    __half *xh_p, *gph_p, *uph_p, *dph_p;
    cudaGetSymbolAddress((void**)&xh_p,  g_xh);
    cudaGetSymbolAddress((void**)&gph_p, g_gph);
    cudaGetSymbolAddress((void**)&uph_p, g_uph);
    cudaGetSymbolAddress((void**)&dph_p, g_dph);

    const size_t W8 = WELEM / 8;                  // 12582912
    const size_t X8 = (size_t)T_TOK * HID / 8;    // 2097152

    k_reset<<<(MAXPAD + 255) / 256, 256>>>();
    k_router<<<T_TOK / 16, 256>>>(x, gw, out_logits, write_logits);
    k_scan<<<1, 32>>>();
    k_fill<<<(TK + 255) / 256, 256>>>();

    // one-time fp32 -> fp16 operand conversion
    k_cvt<<<(unsigned)((X8 + 255) / 256), 256>>>((const float4*)x,  (uint4*)xh_p,  X8);
    k_cvt<<<(unsigned)((W8 + 255) / 256), 256>>>((const float4*)gp, (uint4*)gph_p, W8);
    k_cvt<<<(unsigned)((W8 + 255) / 256), 256>>>((const float4*)up, (uint4*)uph_p, W8);
    k_cvt<<<(unsigned)((W8 + 255) / 256), 256>>>((const float4*)dp, (uint4*)dph_p, W8);

    k_gemm<HID, IDIM, 0><<<dim3(MAX_TILES, IDIM / TILE_N), 256, GEMM_SMEM>>>(xh_p, gph_p);
    k_gemm<HID, IDIM, 1><<<dim3(MAX_TILES, IDIM / TILE_N), 256, GEMM_SMEM>>>(xh_p, uph_p);
    k_gemm<IDIM, HID, 2><<<dim3(MAX_TILES, HID / TILE_N), 256, GEMM_SMEM>>>(xh_p, dph_p);

    k_combine<<<T_TOK * HID / 4 / 256, 256>>>(out);
}

// round 7
// speedup vs baseline: 4.2087x; 1.0819x over previous
#include <cuda_runtime.h>
#include <cuda_fp16.h>
#include <mma.h>
#include <math.h>
#include <stdint.h>

using namespace nvcuda;

// Problem constants
#define T_TOK 8192
#define HID   2048
#define NEXP  64
#define IDIM  768
#define TOPK  8
#define TK    (T_TOK*TOPK)               // 65536 pairs
#define TILE_M 128
#define MAX_TILES ((TK/TILE_M) + NEXP)   // 576
#define MAXPAD (MAX_TILES*TILE_M)        // 73728
#define WELEM  ((size_t)NEXP*IDIM*HID)   // 100663296 per weight tensor

// GEMM geometry
#define BK       64                       // halfs per k-slice (128 B rows)
#define HS_STRIDE 72                      // 64 + 8 pad halfs
#define A_HL     (128*HS_STRIDE)          // 9216 halfs
#define B_HL     (256*HS_STRIDE)          // 18432 halfs
#define ST_HL    (A_HL + B_HL)            // 27648 halfs (55296 B)
#define STAGES   4
#define GEMM_SMEM (STAGES*ST_HL*2)        // 221184 B
#define GU_STRIDE 132                     // fused epilogue fp32 stride (128+4)
#define CS_STRIDE 260                     // down epilogue fp32 stride (256+4)

// ---------------- scratch ----------------
__device__ int    g_topk_e[TK];
__device__ float  g_topk_w[TK];
__device__ int    g_counts[NEXP];
__device__ int    g_cursor[NEXP];
__device__ int    g_tile_expert[MAX_TILES];
__device__ int    g_token_list[MAXPAD];
__device__ int    g_pair_slot[TK];
__device__ __half g_acth[(size_t)MAXPAD * IDIM];    // fp16 act = silu(g)*u
__device__ __half g_pairouth[(size_t)MAXPAD * HID]; // fp16 per-pair down output
// fp16 operand copies
__device__ __half g_xh[(size_t)T_TOK * HID];
__device__ __half g_gph[WELEM];
__device__ __half g_uph[WELEM];
__device__ __half g_dph[WELEM];

// ---------------- cp.async helpers ----------------
__device__ __forceinline__ void cp_async16(uint32_t dst, const void* src, int sz) {
    asm volatile("cp.async.cg.shared.global [%0], [%1], 16, %2;\n" :: "r"(dst), "l"(src), "r"(sz));
}
__device__ __forceinline__ void cp_commit() { asm volatile("cp.async.commit_group;\n"); }
__device__ __forceinline__ void cp_wait2()  { asm volatile("cp.async.wait_group 2;\n"); }

// ---------------- fp32 -> fp16 conversion (8 elems/thread) ----------------
__global__ __launch_bounds__(256) void k_cvt(const float4* __restrict__ s,
                                             uint4* __restrict__ d, size_t n8) {
    size_t i = (size_t)blockIdx.x * 256 + threadIdx.x;
    if (i < n8) {
        float4 a = s[2 * i], b = s[2 * i + 1];
        __half2 h0 = __floats2half2_rn(a.x, a.y);
        __half2 h1 = __floats2half2_rn(a.z, a.w);
        __half2 h2 = __floats2half2_rn(b.x, b.y);
        __half2 h3 = __floats2half2_rn(b.z, b.w);
        uint4 o;
        o.x = *(unsigned*)&h0; o.y = *(unsigned*)&h1;
        o.z = *(unsigned*)&h2; o.w = *(unsigned*)&h3;
        d[i] = o;
    }
}

// ---------------- reset ----------------
__global__ void k_reset() {
    int idx = blockIdx.x * blockDim.x + threadIdx.x;
    if (idx < MAXPAD)    g_token_list[idx] = -1;
    if (idx < MAX_TILES) g_tile_expert[idx] = -1;
    if (idx < NEXP)      g_counts[idx] = 0;
}

// ---------------- router: fp32 logits, softmax, top-8, renorm ----------------
__global__ __launch_bounds__(256) void k_router(
    const float* __restrict__ x, const float* __restrict__ gw,
    float* __restrict__ out_logits, int write_logits)
{
    __shared__ float xs[16 * 64];
    __shared__ float ws[64 * 65];
    __shared__ float lg[16 * 65];

    int tid = threadIdx.x;
    int tok0 = blockIdx.x * 16;
    int e  = tid & 63;
    int tr = tid >> 6;
    float acc0 = 0.f, acc1 = 0.f, acc2 = 0.f, acc3 = 0.f;

    for (int kc = 0; kc < HID; kc += 64) {
        {
            int r  = tid >> 4;
            int c4 = tid & 15;
            float4 v = *(const float4*)(x + (size_t)(tok0 + r) * HID + kc + c4 * 4);
            *(float4*)&xs[r * 64 + c4 * 4] = v;
        }
        #pragma unroll
        for (int p = 0; p < 16; p++) {
            int lin = p * 256 + tid;
            int r = lin >> 6, c = lin & 63;
            ws[r * 65 + c] = gw[(size_t)r * HID + kc + c];
        }
        __syncthreads();
        #pragma unroll 8
        for (int kk = 0; kk < 64; kk++) {
            float wv = ws[e * 65 + kk];
            acc0 += xs[(tr * 4 + 0) * 64 + kk] * wv;
            acc1 += xs[(tr * 4 + 1) * 64 + kk] * wv;
            acc2 += xs[(tr * 4 + 2) * 64 + kk] * wv;
            acc3 += xs[(tr * 4 + 3) * 64 + kk] * wv;
        }
        __syncthreads();
    }
    lg[(tr * 4 + 0) * 65 + e] = acc0;
    lg[(tr * 4 + 1) * 65 + e] = acc1;
    lg[(tr * 4 + 2) * 65 + e] = acc2;
    lg[(tr * 4 + 3) * 65 + e] = acc3;
    __syncthreads();

    if (write_logits) {
        #pragma unroll
        for (int p = 0; p < 4; p++) {
            int lin = p * 256 + tid;
            int t = lin >> 6, ee = lin & 63;
            out_logits[(size_t)(tok0 + t) * NEXP + ee] = lg[t * 65 + ee];
        }
    }

    if (tid < 16) {
        int t = tid;
        float* l = &lg[t * 65];
        float m = -1e30f;
        for (int i = 0; i < NEXP; i++) m = fmaxf(m, l[i]);
        for (int i = 0; i < NEXP; i++) l[i] = expf(l[i] - m);
        int   sel[TOPK];
        float sp[TOPK];
        float wsum = 0.f;
        #pragma unroll
        for (int k = 0; k < TOPK; k++) {
            float bp = -1.f; int be = -1;
            for (int i = 0; i < NEXP; i++)
                if (l[i] > bp) { bp = l[i]; be = i; }
            sel[k] = be; sp[k] = bp; wsum += bp;
            l[be] = -1.f;
        }
        float inv = 1.f / wsum;
        #pragma unroll
        for (int k = 0; k < TOPK; k++) {
            int idx = (tok0 + t) * TOPK + k;
            g_topk_e[idx] = sel[k];
            g_topk_w[idx] = sp[k] * inv;
            atomicAdd(&g_counts[sel[k]], 1);
        }
    }
}

// ---------------- scan ----------------
__global__ void k_scan() {
    if (threadIdx.x == 0 && blockIdx.x == 0) {
        int tile = 0;
        for (int e = 0; e < NEXP; e++) {
            int n = g_counts[e];
            g_cursor[e] = tile * TILE_M;
            int nt = (n + TILE_M - 1) / TILE_M;
            for (int i = 0; i < nt; i++) g_tile_expert[tile + i] = e;
            tile += nt;
        }
    }
}

// ---------------- fill ----------------
__global__ void k_fill() {
    int idx = blockIdx.x * blockDim.x + threadIdx.x;
    if (idx < TK) {
        int e = g_topk_e[idx];
        int p = atomicAdd(&g_cursor[e], 1);
        g_token_list[p] = idx >> 3;
        g_pair_slot[idx] = p;
    }
}

typedef wmma::fragment<wmma::matrix_a, 16, 16, 16, __half, wmma::row_major> FragA;
typedef wmma::fragment<wmma::matrix_b, 16, 16, 16, __half, wmma::col_major> FragB;
typedef wmma::fragment<wmma::accumulator, 16, 16, 16, float> FragC;

// ---------------- fused gate+up GEMM -------------------------------------
// block: 128 M-rows x 128 N-cols of BOTH gate and up; grid (MAX_TILES, IDIM/128)
// g_acth = fp16( silu(X@gp^T) * (X@up^T) )
__global__ __launch_bounds__(256, 1) void k_gemm_gu(
    const __half* __restrict__ Xh,
    const __half* __restrict__ Gp, const __half* __restrict__ Up)
{
    extern __shared__ __half smh[];
    __shared__ int toks[TILE_M];

    int tileM = blockIdx.x;
    int eid = g_tile_expert[tileM];
    if (eid < 0) return;
    int slot0 = tileM * TILE_M;
    int n0 = blockIdx.y * 128;
    const __half* Gexp = Gp + (size_t)eid * IDIM * HID;
    const __half* Uexp = Up + (size_t)eid * IDIM * HID;

    int tid = threadIdx.x;
    if (tid < TILE_M) toks[tid] = g_token_list[slot0 + tid];
    __syncthreads();

    uint32_t s_base = (uint32_t)__cvta_generic_to_shared(smh);

    // stage: A 128x64h; B rows 0-127 = gate[n0..n0+127], rows 128-255 = up[...]
    auto issue = [&](int s, int k0) {
        uint32_t ab = s_base + (uint32_t)(s * ST_HL) * 2;
        uint32_t bb = ab + (uint32_t)A_HL * 2;
        #pragma unroll
        for (int p = 0; p < 4; p++) {
            int lin = p * 256 + tid;
            int r = lin >> 3, c = lin & 7;
            uint32_t doff = (uint32_t)(r * HS_STRIDE + c * 8) * 2;
            int tk = toks[r];
            const __half* src = Xh + (size_t)(tk < 0 ? 0 : tk) * HID + k0 + c * 8;
            cp_async16(ab + doff, src, (tk < 0) ? 0 : 16);
        }
        #pragma unroll
        for (int p = 0; p < 8; p++) {
            int lin = p * 256 + tid;
            int r = lin >> 3, c = lin & 7;
            uint32_t doff = (uint32_t)(r * HS_STRIDE + c * 8) * 2;
            const __half* src = (r < 128)
                ? Gexp + (size_t)(n0 + r) * HID + k0 + c * 8
                : Uexp + (size_t)(n0 + r - 128) * HID + k0 + c * 8;
            cp_async16(bb + doff, src, 16);
        }
        cp_commit();
    };

    FragC cg[4][2], cu[4][2];
    #pragma unroll
    for (int i = 0; i < 4; i++)
        #pragma unroll
        for (int j = 0; j < 2; j++) {
            wmma::fill_fragment(cg[i][j], 0.f);
            wmma::fill_fragment(cu[i][j], 0.f);
        }

    int wid = tid >> 5;
    int wm = wid & 1;          // M half: rows wm*64
    int wn = wid >> 1;         // N quarter: cols wn*32

    const int KT = HID / BK;   // 32
    issue(0, 0);
    issue(1, BK);
    issue(2, 2 * BK);

    for (int kt = 0; kt < KT; kt++) {
        cp_wait2();
        __syncthreads();
        if (kt + 3 < KT) issue((kt + 3) % STAGES, (kt + 3) * BK);

        __half* As = smh + (kt % STAGES) * ST_HL;
        __half* Bs = As + A_HL;

        #pragma unroll
        for (int kk = 0; kk < BK; kk += 16) {
            FragA a[4];
            FragB bg[2], bu[2];
            #pragma unroll
            for (int i = 0; i < 4; i++)
                wmma::load_matrix_sync(a[i], As + (wm * 64 + i * 16) * HS_STRIDE + kk, HS_STRIDE);
            #pragma unroll
            for (int j = 0; j < 2; j++) {
                wmma::load_matrix_sync(bg[j], Bs + (wn * 32 + j * 16) * HS_STRIDE + kk, HS_STRIDE);
                wmma::load_matrix_sync(bu[j], Bs + (128 + wn * 32 + j * 16) * HS_STRIDE + kk, HS_STRIDE);
            }
            #pragma unroll
            for (int i = 0; i < 4; i++)
                #pragma unroll
                for (int j = 0; j < 2; j++) {
                    wmma::mma_sync(cg[i][j], a[i], bg[j], cg[i][j]);
                    wmma::mma_sync(cu[i][j], a[i], bu[j], cu[i][j]);
                }
        }
        __syncthreads();
    }

    // epilogue: stage g and u (fp32) in smem, fuse act = fp16(silu(g)*u)
    float* Gs = (float*)smh;                 // 128 x GU_STRIDE
    float* Us = Gs + 128 * GU_STRIDE;        // 128 x GU_STRIDE (total 135168 B)
    #pragma unroll
    for (int i = 0; i < 4; i++)
        #pragma unroll
        for (int j = 0; j < 2; j++) {
            wmma::store_matrix_sync(Gs + (wm * 64 + i * 16) * GU_STRIDE + wn * 32 + j * 16,
                                    cg[i][j], GU_STRIDE, wmma::mem_row_major);
            wmma::store_matrix_sync(Us + (wm * 64 + i * 16) * GU_STRIDE + wn * 32 + j * 16,
                                    cu[i][j], GU_STRIDE, wmma::mem_row_major);
        }
    __syncthreads();
    #pragma unroll
    for (int p = 0; p < 16; p++) {
        int lin = p * 256 + tid;             // 4096 groups of 4
        int m = lin >> 5, n4 = lin & 31;
        float4 g = *(float4*)(Gs + m * GU_STRIDE + n4 * 4);
        float4 u = *(float4*)(Us + m * GU_STRIDE + n4 * 4);
        float ax = (g.x / (1.f + expf(-g.x))) * u.x;
        float ay = (g.y / (1.f + expf(-g.y))) * u.y;
        float az = (g.z / (1.f + expf(-g.z))) * u.z;
        float aw = (g.w / (1.f + expf(-g.w))) * u.w;
        __half2 h0 = __floats2half2_rn(ax, ay);
        __half2 h1 = __floats2half2_rn(az, aw);
        uint2 o; o.x = *(unsigned*)&h0; o.y = *(unsigned*)&h1;
        *(uint2*)(g_acth + (size_t)(slot0 + m) * IDIM + n0 + n4 * 4) = o;
    }
}

// ---------------- down GEMM: g_pairouth = fp16(g_acth @ dp[e]^T) ----------
// block 128x256; grid (MAX_TILES, HID/256)
__global__ __launch_bounds__(256, 1) void k_gemm_down(const __half* __restrict__ Dp)
{
    extern __shared__ __half smh[];

    int tileM = blockIdx.x;
    int eid = g_tile_expert[tileM];
    if (eid < 0) return;
    int slot0 = tileM * TILE_M;
    int n0 = blockIdx.y * 256;
    const __half* Bexp = Dp + (size_t)eid * HID * IDIM;

    int tid = threadIdx.x;
    uint32_t s_base = (uint32_t)__cvta_generic_to_shared(smh);

    auto issue = [&](int s, int k0) {
        uint32_t ab = s_base + (uint32_t)(s * ST_HL) * 2;
        uint32_t bb = ab + (uint32_t)A_HL * 2;
        #pragma unroll
        for (int p = 0; p < 4; p++) {
            int lin = p * 256 + tid;
            int r = lin >> 3, c = lin & 7;
            uint32_t doff = (uint32_t)(r * HS_STRIDE + c * 8) * 2;
            cp_async16(ab + doff, g_acth + (size_t)(slot0 + r) * IDIM + k0 + c * 8, 16);
        }
        #pragma unroll
        for (int p = 0; p < 8; p++) {
            int lin = p * 256 + tid;
            int r = lin >> 3, c = lin & 7;
            uint32_t doff = (uint32_t)(r * HS_STRIDE + c * 8) * 2;
            cp_async16(bb + doff, Bexp + (size_t)(n0 + r) * IDIM + k0 + c * 8, 16);
        }
        cp_commit();
    };

    FragC c[4][4];
    #pragma unroll
    for (int i = 0; i < 4; i++)
        #pragma unroll
        for (int j = 0; j < 4; j++)
            wmma::fill_fragment(c[i][j], 0.f);

    int wid = tid >> 5;
    int wm = wid & 1;
    int wn = wid >> 1;

    const int KT = IDIM / BK;   // 12
    issue(0, 0);
    issue(1, BK);
    issue(2, 2 * BK);

    for (int kt = 0; kt < KT; kt++) {
        cp_wait2();
        __syncthreads();
        if (kt + 3 < KT) issue((kt + 3) % STAGES, (kt + 3) * BK);

        __half* As = smh + (kt % STAGES) * ST_HL;
        __half* Bs = As + A_HL;

        #pragma unroll
        for (int kk = 0; kk < BK; kk += 16) {
            FragA a[4];
            FragB b[4];
            #pragma unroll
            for (int i = 0; i < 4; i++)
                wmma::load_matrix_sync(a[i], As + (wm * 64 + i * 16) * HS_STRIDE + kk, HS_STRIDE);
            #pragma unroll
            for (int j = 0; j < 4; j++)
                wmma::load_matrix_sync(b[j], Bs + (wn * 64 + j * 16) * HS_STRIDE + kk, HS_STRIDE);
            #pragma unroll
            for (int i = 0; i < 4; i++)
                #pragma unroll
                for (int j = 0; j < 4; j++)
                    wmma::mma_sync(c[i][j], a[i], b[j], c[i][j]);
        }
        __syncthreads();
    }

    // epilogue: stage fp32, convert, write fp16 pairout
    float* Cs = (float*)smh;                 // 128 x CS_STRIDE
    #pragma unroll
    for (int i = 0; i < 4; i++)
        #pragma unroll
        for (int j = 0; j < 4; j++)
            wmma::store_matrix_sync(Cs + (wm * 64 + i * 16) * CS_STRIDE + wn * 64 + j * 16,
                                    c[i][j], CS_STRIDE, wmma::mem_row_major);
    __syncthreads();
    #pragma unroll
    for (int p = 0; p < 16; p++) {
        int lin = p * 256 + tid;             // 4096 groups of 8
        int m = lin >> 5, n8 = lin & 31;
        float4 v0 = *(float4*)(Cs + m * CS_STRIDE + n8 * 8);
        float4 v1 = *(float4*)(Cs + m * CS_STRIDE + n8 * 8 + 4);
        __half2 h0 = __floats2half2_rn(v0.x, v0.y);
        __half2 h1 = __floats2half2_rn(v0.z, v0.w);
        __half2 h2 = __floats2half2_rn(v1.x, v1.y);
        __half2 h3 = __floats2half2_rn(v1.z, v1.w);
        uint4 o;
        o.x = *(unsigned*)&h0; o.y = *(unsigned*)&h1;
        o.z = *(unsigned*)&h2; o.w = *(unsigned*)&h3;
        *(uint4*)(g_pairouth + (size_t)(slot0 + m) * HID + n0 + n8 * 8) = o;
    }
}

// ---------------- combine (reads fp16 pairout, fp32 accumulate) ----------
__global__ __launch_bounds__(256) void k_combine(float* __restrict__ out) {
    size_t idx = (size_t)blockIdx.x * 256 + threadIdx.x;   // over T*H/8
    int t  = (int)(idx >> 8);           // / (HID/8)
    int h8 = (int)(idx & 255);
    float s[8] = {0.f};
    #pragma unroll
    for (int k = 0; k < TOPK; k++) {
        int pi = t * TOPK + k;
        int p = g_pair_slot[pi];
        float w = g_topk_w[pi];
        uint4 v = *(const uint4*)(g_pairouth + (size_t)p * HID + h8 * 8);
        __half2 h0 = *(__half2*)&v.x, h1 = *(__half2*)&v.y;
        __half2 h2 = *(__half2*)&v.z, h3 = *(__half2*)&v.w;
        float2 f0 = __half22float2(h0), f1 = __half22float2(h1);
        float2 f2 = __half22float2(h2), f3 = __half22float2(h3);
        s[0] += w * f0.x; s[1] += w * f0.y; s[2] += w * f1.x; s[3] += w * f1.y;
        s[4] += w * f2.x; s[5] += w * f2.y; s[6] += w * f3.x; s[7] += w * f3.y;
    }
    float4 o0 = make_float4(s[0], s[1], s[2], s[3]);
    float4 o1 = make_float4(s[4], s[5], s[6], s[7]);
    *(float4*)(out + idx * 8)     = o0;
    *(float4*)(out + idx * 8 + 4) = o1;
}

// ---------------- launch ----------------
extern "C" void kernel_launch(void* const* d_in, const int* in_sizes, int n_in,
                              void* d_out, int out_size) {
    const float* x  = (const float*)d_in[0];
    const float* gw = (const float*)d_in[1];
    const float* gp = (const float*)d_in[2];
    const float* up = (const float*)d_in[3];
    const float* dp = (const float*)d_in[4];
    float* out = (float*)d_out;
    float* out_logits = out + (size_t)T_TOK * HID;
    int write_logits = (out_size >= T_TOK * HID + T_TOK * NEXP) ? 1 : 0;

    cudaFuncSetAttribute(k_gemm_gu,
                         cudaFuncAttributeMaxDynamicSharedMemorySize, GEMM_SMEM);
    cudaFuncSetAttribute(k_gemm_down,
                         cudaFuncAttributeMaxDynamicSharedMemorySize, GEMM_SMEM);

    __half *xh_p, *gph_p, *uph_p, *dph_p;
    cudaGetSymbolAddress((void**)&xh_p,  g_xh);
    cudaGetSymbolAddress((void**)&gph_p, g_gph);
    cudaGetSymbolAddress((void**)&uph_p, g_uph);
    cudaGetSymbolAddress((void**)&dph_p, g_dph);

    const size_t W8 = WELEM / 8;
    const size_t X8 = (size_t)T_TOK * HID / 8;

    k_reset<<<(MAXPAD + 255) / 256, 256>>>();
    k_router<<<T_TOK / 16, 256>>>(x, gw, out_logits, write_logits);
    k_scan<<<1, 32>>>();
    k_fill<<<(TK + 255) / 256, 256>>>();

    k_cvt<<<(unsigned)((X8 + 255) / 256), 256>>>((const float4*)x,  (uint4*)xh_p,  X8);
    k_cvt<<<(unsigned)((W8 + 255) / 256), 256>>>((const float4*)gp, (uint4*)gph_p, W8);
    k_cvt<<<(unsigned)((W8 + 255) / 256), 256>>>((const float4*)up, (uint4*)uph_p, W8);
    k_cvt<<<(unsigned)((W8 + 255) / 256), 256>>>((const float4*)dp, (uint4*)dph_p, W8);

    k_gemm_gu<<<dim3(MAX_TILES, IDIM / 128), 256, GEMM_SMEM>>>(xh_p, gph_p, uph_p);
    k_gemm_down<<<dim3(MAX_TILES, HID / 256), 256, GEMM_SMEM>>>(dph_p);

    k_combine<<<T_TOK * HID / 8 / 256, 256>>>(out);
}